// round 1
// baseline (speedup 1.0000x reference)
#include <cuda_runtime.h>
#include <cuda_bf16.h>
#include <cstdint>

#define BATCH 4
#define SEQ   2048
#define DM    1024
#define NHEAD 16
#define DK    64

// ---------------- scratch (no allocations allowed) ----------------
__device__ float g_qproj[BATCH * SEQ * DM];
__device__ float g_kproj[BATCH * SEQ * DM];
__device__ float g_vproj[BATCH * SEQ * DM];
__device__ float g_ctx  [BATCH * SEQ * DM];

// ---------------- SGEMM: Y[M,N] = X[M,K] @ W[N,K]^T ----------------
// 128x128 tile, BK=8, 256 threads, 8x8 per-thread register tile.
__global__ __launch_bounds__(256) void sgemm_xwt(
    const float* __restrict__ X, const float* __restrict__ W,
    float* __restrict__ Y, int M, int N, int K)
{
    __shared__ float As[8][128];
    __shared__ float Bs[8][128];

    const int tid  = threadIdx.x;
    const int brow = blockIdx.y * 128;
    const int bcol = blockIdx.x * 128;

    // global load mapping: each thread loads one float4 of A and one of B
    const int lrow = tid >> 1;        // 0..127
    const int lk   = (tid & 1) * 4;   // 0 or 4

    const float* Xp = X + (size_t)(brow + lrow) * K + lk;
    const float* Wp = W + (size_t)(bcol + lrow) * K + lk;

    const int ty = tid >> 4;          // 0..15
    const int tx = tid & 15;          // 0..15

    float acc[8][8];
#pragma unroll
    for (int i = 0; i < 8; i++)
#pragma unroll
        for (int j = 0; j < 8; j++) acc[i][j] = 0.0f;

    for (int k0 = 0; k0 < K; k0 += 8) {
        float4 a = *(const float4*)(Xp + k0);
        float4 b = *(const float4*)(Wp + k0);
        __syncthreads();   // protect smem from previous iteration's readers
        As[lk + 0][lrow] = a.x; As[lk + 1][lrow] = a.y;
        As[lk + 2][lrow] = a.z; As[lk + 3][lrow] = a.w;
        Bs[lk + 0][lrow] = b.x; Bs[lk + 1][lrow] = b.y;
        Bs[lk + 2][lrow] = b.z; Bs[lk + 3][lrow] = b.w;
        __syncthreads();

#pragma unroll
        for (int kk = 0; kk < 8; kk++) {
            float af[8], bf[8];
#pragma unroll
            for (int i = 0; i < 8; i++) af[i] = As[kk][ty * 8 + i];
#pragma unroll
            for (int j = 0; j < 8; j++) bf[j] = Bs[kk][tx * 8 + j];
#pragma unroll
            for (int i = 0; i < 8; i++)
#pragma unroll
                for (int j = 0; j < 8; j++)
                    acc[i][j] = fmaf(af[i], bf[j], acc[i][j]);
        }
    }

    float* Yp = Y + (size_t)(brow + ty * 8) * N + bcol + tx * 8;
#pragma unroll
    for (int i = 0; i < 8; i++) {
        *(float4*)(Yp + (size_t)i * N + 0) =
            make_float4(acc[i][0], acc[i][1], acc[i][2], acc[i][3]);
        *(float4*)(Yp + (size_t)i * N + 4) =
            make_float4(acc[i][4], acc[i][5], acc[i][6], acc[i][7]);
    }
}

// ---------------- causal flash attention ----------------
// grid: (SEQ/64, NHEAD, BATCH); 256 threads; 64x64 Q-tile, 64x64 K/V tiles.
// Q/K/V live in the projection buffers laid out [B*S, DM], head h at col h*64.
#define FA_PAD 65
#define FA_SMEM (4 * 64 * FA_PAD * sizeof(float))

__global__ __launch_bounds__(256) void flash_attn(
    const float* __restrict__ Qp, const float* __restrict__ Kp,
    const float* __restrict__ Vp, float* __restrict__ Ctx)
{
    extern __shared__ float smem[];
    float (*Qs)[FA_PAD] = (float (*)[FA_PAD])(smem);
    float (*Ks)[FA_PAD] = (float (*)[FA_PAD])(smem + 64 * FA_PAD);
    float (*Vs)[FA_PAD] = (float (*)[FA_PAD])(smem + 2 * 64 * FA_PAD);
    float (*Ps)[FA_PAD] = (float (*)[FA_PAD])(smem + 3 * 64 * FA_PAD);

    const int qi = blockIdx.x;          // q-tile index 0..31
    const int h  = blockIdx.y;
    const int b  = blockIdx.z;
    const int q0 = qi * 64;

    const int tid = threadIdx.x;
    const int ty = tid >> 4, tx = tid & 15;
    const int rbase = ty * 4, cbase = tx * 4;

    const float scale = 0.125f;         // 1/sqrt(64)
    const size_t base = (size_t)b * SEQ * DM + (size_t)h * DK;

    // load Q tile (64 rows x 64 cols)
    for (int i = tid; i < 64 * 16; i += 256) {
        int r = i >> 4, c4 = (i & 15) * 4;
        float4 qv = *(const float4*)(Qp + base + (size_t)(q0 + r) * DM + c4);
        Qs[r][c4 + 0] = qv.x; Qs[r][c4 + 1] = qv.y;
        Qs[r][c4 + 2] = qv.z; Qs[r][c4 + 3] = qv.w;
    }

    float m_i[4], l_i[4], acc[4][4];
#pragma unroll
    for (int i = 0; i < 4; i++) {
        m_i[i] = -1e30f; l_i[i] = 0.0f;
#pragma unroll
        for (int j = 0; j < 4; j++) acc[i][j] = 0.0f;
    }

    for (int jt = 0; jt <= qi; jt++) {
        const int k0 = jt * 64;
        __syncthreads();   // previous iteration done reading Ks/Vs/Ps
        for (int i = tid; i < 64 * 16; i += 256) {
            int r = i >> 4, c4 = (i & 15) * 4;
            float4 kv = *(const float4*)(Kp + base + (size_t)(k0 + r) * DM + c4);
            Ks[r][c4 + 0] = kv.x; Ks[r][c4 + 1] = kv.y;
            Ks[r][c4 + 2] = kv.z; Ks[r][c4 + 3] = kv.w;
            float4 vv = *(const float4*)(Vp + base + (size_t)(k0 + r) * DM + c4);
            Vs[r][c4 + 0] = vv.x; Vs[r][c4 + 1] = vv.y;
            Vs[r][c4 + 2] = vv.z; Vs[r][c4 + 3] = vv.w;
        }
        __syncthreads();

        // S = scale * Q @ K^T  (each thread: 4x4 of the 64x64 score tile)
        float s[4][4];
#pragma unroll
        for (int i = 0; i < 4; i++)
#pragma unroll
            for (int j = 0; j < 4; j++) s[i][j] = 0.0f;

#pragma unroll 8
        for (int d = 0; d < 64; d++) {
            float af[4], bf[4];
#pragma unroll
            for (int i = 0; i < 4; i++) af[i] = Qs[rbase + i][d];
#pragma unroll
            for (int j = 0; j < 4; j++) bf[j] = Ks[cbase + j][d];
#pragma unroll
            for (int i = 0; i < 4; i++)
#pragma unroll
                for (int j = 0; j < 4; j++)
                    s[i][j] = fmaf(af[i], bf[j], s[i][j]);
        }

        const bool diag = (jt == qi);
#pragma unroll
        for (int i = 0; i < 4; i++)
#pragma unroll
            for (int j = 0; j < 4; j++) {
                s[i][j] *= scale;
                if (diag && (k0 + cbase + j) > (q0 + rbase + i)) s[i][j] = -1e30f;
            }

        float alpha[4];
#pragma unroll
        for (int i = 0; i < 4; i++) {
            float ml = fmaxf(fmaxf(s[i][0], s[i][1]), fmaxf(s[i][2], s[i][3]));
#pragma unroll
            for (int off = 8; off >= 1; off >>= 1)
                ml = fmaxf(ml, __shfl_xor_sync(0xffffffffu, ml, off));
            float mn = fmaxf(m_i[i], ml);
            alpha[i] = __expf(m_i[i] - mn);
            float rs = 0.0f;
#pragma unroll
            for (int j = 0; j < 4; j++) {
                float p = __expf(s[i][j] - mn);
                Ps[rbase + i][cbase + j] = p;
                rs += p;
            }
#pragma unroll
            for (int off = 8; off >= 1; off >>= 1)
                rs += __shfl_xor_sync(0xffffffffu, rs, off);
            l_i[i] = l_i[i] * alpha[i] + rs;
            m_i[i] = mn;
        }
        __syncthreads();   // Ps visible to everyone

        // acc = acc*alpha + P @ V  (thread owns rows rbase..+3, dims cbase..+3)
#pragma unroll
        for (int i = 0; i < 4; i++)
#pragma unroll
            for (int j = 0; j < 4; j++) acc[i][j] *= alpha[i];

#pragma unroll 8
        for (int c = 0; c < 64; c++) {
            float pf[4], vf[4];
#pragma unroll
            for (int i = 0; i < 4; i++) pf[i] = Ps[rbase + i][c];
#pragma unroll
            for (int j = 0; j < 4; j++) vf[j] = Vs[c][cbase + j];
#pragma unroll
            for (int i = 0; i < 4; i++)
#pragma unroll
                for (int j = 0; j < 4; j++)
                    acc[i][j] = fmaf(pf[i], vf[j], acc[i][j]);
        }
    }

    // write ctx in [B*S, DM] layout (head h at column h*64)
#pragma unroll
    for (int i = 0; i < 4; i++) {
        float inv_l = 1.0f / l_i[i];
#pragma unroll
        for (int j = 0; j < 4; j++)
            Ctx[base + (size_t)(q0 + rbase + i) * DM + cbase + j] = acc[i][j] * inv_l;
    }
}

// ---------------- launch ----------------
extern "C" void kernel_launch(void* const* d_in, const int* in_sizes, int n_in,
                              void* d_out, int out_size)
{
    const float* q  = (const float*)d_in[0];
    const float* k  = (const float*)d_in[1];
    const float* v  = (const float*)d_in[2];
    // d_in[3] = mask: causal, hardcoded in flash_attn
    const float* Wq = (const float*)d_in[4];
    const float* Wk = (const float*)d_in[5];
    const float* Wv = (const float*)d_in[6];
    const float* Wo = (const float*)d_in[7];
    float* out = (float*)d_out;

    float *qp, *kp, *vp, *ctx;
    cudaGetSymbolAddress((void**)&qp,  g_qproj);
    cudaGetSymbolAddress((void**)&kp,  g_kproj);
    cudaGetSymbolAddress((void**)&vp,  g_vproj);
    cudaGetSymbolAddress((void**)&ctx, g_ctx);

    cudaFuncSetAttribute(flash_attn, cudaFuncAttributeMaxDynamicSharedMemorySize,
                         (int)FA_SMEM);

    const int M = BATCH * SEQ;              // 8192
    dim3 gg(DM / 128, M / 128);             // (8, 64)

    sgemm_xwt<<<gg, 256>>>(q, Wq, qp, M, DM, DM);
    sgemm_xwt<<<gg, 256>>>(k, Wk, kp, M, DM, DM);
    sgemm_xwt<<<gg, 256>>>(v, Wv, vp, M, DM, DM);

    flash_attn<<<dim3(SEQ / 64, NHEAD, BATCH), 256, FA_SMEM>>>(qp, kp, vp, ctx);

    sgemm_xwt<<<gg, 256>>>(ctx, Wo, out, M, DM, DM);
}

// round 3
// speedup vs baseline: 1.5659x; 1.5659x over previous
#include <cuda_runtime.h>
#include <cuda_bf16.h>
#include <cstdint>

#define BATCH 4
#define SEQ   2048
#define DM    1024
#define NHEAD 16
#define DK    64
#define MTOT  (BATCH * SEQ)   // 8192

// ---------------- scratch (no allocations allowed) ----------------
__device__ float g_qproj[MTOT * DM];
__device__ float g_kproj[MTOT * DM];
__device__ float g_vproj[MTOT * DM];
__device__ float g_ctx  [MTOT * DM];
__device__ __nv_bfloat16 g_ahi[MTOT * DM];
__device__ __nv_bfloat16 g_alo[MTOT * DM];
__device__ __nv_bfloat16 g_bhi[DM * DM];
__device__ __nv_bfloat16 g_blo[DM * DM];

// ---------------- PTX helpers (base sm_103 ISA only) ----------------
__device__ __forceinline__ uint32_t smem_u32(const void* p) {
    uint32_t a;
    asm("{ .reg .u64 t; cvta.to.shared.u64 t, %1; cvt.u32.u64 %0, t; }"
        : "=r"(a) : "l"(p));
    return a;
}

__device__ __forceinline__ void cp16(uint32_t dst, const void* src) {
    asm volatile("cp.async.cg.shared.global [%0], [%1], 16;"
                 :: "r"(dst), "l"(src));
}

__device__ __forceinline__ void ldsm4(uint32_t& r0, uint32_t& r1,
                                      uint32_t& r2, uint32_t& r3, uint32_t addr) {
    asm volatile("ldmatrix.sync.aligned.m8n8.x4.shared.b16 {%0,%1,%2,%3}, [%4];"
                 : "=r"(r0), "=r"(r1), "=r"(r2), "=r"(r3) : "r"(addr));
}

__device__ __forceinline__ void mma16816(float* c, const uint32_t* a,
                                         uint32_t b0, uint32_t b1) {
    asm volatile(
        "mma.sync.aligned.m16n8k16.row.col.f32.bf16.bf16.f32 "
        "{%0,%1,%2,%3}, {%4,%5,%6,%7}, {%8,%9}, {%0,%1,%2,%3};"
        : "+f"(c[0]), "+f"(c[1]), "+f"(c[2]), "+f"(c[3])
        : "r"(a[0]), "r"(a[1]), "r"(a[2]), "r"(a[3]), "r"(b0), "r"(b1));
}

// ---------------- fp32 -> bf16 hi/lo split ----------------
__global__ __launch_bounds__(256) void cvt_split(
    const float* __restrict__ x, __nv_bfloat16* __restrict__ hi,
    __nv_bfloat16* __restrict__ lo, int n4)
{
    int i = blockIdx.x * 256 + threadIdx.x;
    if (i >= n4) return;
    float4 v = ((const float4*)x)[i];
    __nv_bfloat16 h0 = __float2bfloat16(v.x);
    __nv_bfloat16 h1 = __float2bfloat16(v.y);
    __nv_bfloat16 h2 = __float2bfloat16(v.z);
    __nv_bfloat16 h3 = __float2bfloat16(v.w);
    __nv_bfloat16 l0 = __float2bfloat16(v.x - __bfloat162float(h0));
    __nv_bfloat16 l1 = __float2bfloat16(v.y - __bfloat162float(h1));
    __nv_bfloat16 l2 = __float2bfloat16(v.z - __bfloat162float(h2));
    __nv_bfloat16 l3 = __float2bfloat16(v.w - __bfloat162float(h3));
    __nv_bfloat162* hp = (__nv_bfloat162*)hi;
    __nv_bfloat162* lp = (__nv_bfloat162*)lo;
    hp[2 * i]     = __nv_bfloat162(h0, h1);
    hp[2 * i + 1] = __nv_bfloat162(h2, h3);
    lp[2 * i]     = __nv_bfloat162(l0, l1);
    lp[2 * i + 1] = __nv_bfloat162(l2, l3);
}

// ---------------- mma.sync GEMM: Y[M,N] = A[M,K] @ B[N,K]^T, bf16x3 ----------------
// CTA tile 128x128, BK=32, 256 threads (8 warps, 2x4, warp tile 64x32),
// double-buffered cp.async, padded smem (row stride 40 bf16 = 80B).
#define BK        32
#define ROW_BF16  40                     // 32 + 8 pad
#define ROW_B     (ROW_BF16 * 2)         // 80 bytes
#define MAT_B     (128 * ROW_B)          // 10240 bytes per matrix tile
#define STAGE_B   (4 * MAT_B)            // Ahi, Alo, Bhi, Blo
#define GEMM_SMEM (2 * STAGE_B)          // 81920

__global__ __launch_bounds__(256, 1)
void gemm_bf16x3(const __nv_bfloat16* __restrict__ Ahi,
                 const __nv_bfloat16* __restrict__ Alo,
                 const __nv_bfloat16* __restrict__ Bhi,
                 const __nv_bfloat16* __restrict__ Blo,
                 float* __restrict__ Y)
{
    extern __shared__ __align__(128) char smem[];
    const int K = 1024, N = 1024;
    const int tid = threadIdx.x;
    const int w   = tid >> 5, lid = tid & 31;
    const int wm  = w >> 2,  wn  = w & 3;       // warp grid 2x4
    const int brow = blockIdx.y * 128, bcol = blockIdx.x * 128;
    const uint32_t sb = smem_u32(smem);

    const __nv_bfloat16* src[4] = {
        Ahi + (size_t)brow * K, Alo + (size_t)brow * K,
        Bhi + (size_t)bcol * K, Blo + (size_t)bcol * K };

    // ldmatrix lane address offsets (within a matrix tile, for a 16x16 block)
    const uint32_t lrow = lid & 15;             // 0..15
    const uint32_t lcol = (lid >> 4) * 16;      // 0 or 16 bytes

    auto load_stage = [&](int s) {
        const uint32_t base = sb + (s & 1) * STAGE_B;
        const int k0 = s * BK;
#pragma unroll
        for (int t = 0; t < 8; t++) {
            int i = tid + t * 256;              // 0..2047
            int m = i >> 9;                     // matrix 0..3
            int rem = i & 511;
            int r = rem >> 2, c = rem & 3;      // row 0..127, 16B chunk 0..3
            cp16(base + m * MAT_B + r * ROW_B + c * 16,
                 src[m] + k0 + (size_t)r * K + c * 8);
        }
        asm volatile("cp.async.commit_group;" ::: "memory");
    };

    float acc[4][4][4];
#pragma unroll
    for (int mt = 0; mt < 4; mt++)
#pragma unroll
        for (int nt = 0; nt < 4; nt++)
#pragma unroll
            for (int r = 0; r < 4; r++) acc[mt][nt][r] = 0.0f;

    load_stage(0);

    for (int s = 0; s < 32; s++) {
        if (s + 1 < 32) {
            load_stage(s + 1);
            asm volatile("cp.async.wait_group 1;" ::: "memory");
        } else {
            asm volatile("cp.async.wait_group 0;" ::: "memory");
        }
        __syncthreads();

        const uint32_t base = sb + (s & 1) * STAGE_B;
        const uint32_t ah_base = base;
        const uint32_t al_base = base + MAT_B;
        const uint32_t bh_base = base + 2 * MAT_B;
        const uint32_t bl_base = base + 3 * MAT_B;

#pragma unroll
        for (int ks = 0; ks < 2; ks++) {
            const uint32_t kb = ks * 32 + lcol;
            uint32_t ah[4][4], al[4][4], bh[2][4], bl[2][4];
#pragma unroll
            for (int mt = 0; mt < 4; mt++) {
                uint32_t ra = (wm * 64 + mt * 16 + lrow) * ROW_B + kb;
                ldsm4(ah[mt][0], ah[mt][1], ah[mt][2], ah[mt][3], ah_base + ra);
                ldsm4(al[mt][0], al[mt][1], al[mt][2], al[mt][3], al_base + ra);
            }
#pragma unroll
            for (int g = 0; g < 2; g++) {
                uint32_t rb = (wn * 32 + g * 16 + lrow) * ROW_B + kb;
                ldsm4(bh[g][0], bh[g][1], bh[g][2], bh[g][3], bh_base + rb);
                ldsm4(bl[g][0], bl[g][1], bl[g][2], bl[g][3], bl_base + rb);
            }
#pragma unroll
            for (int mt = 0; mt < 4; mt++)
#pragma unroll
                for (int nt = 0; nt < 4; nt++) {
                    const int g = nt >> 1, o = nt & 1;
                    mma16816(acc[mt][nt], ah[mt], bh[g][o], bh[g][o + 2]);
                    mma16816(acc[mt][nt], ah[mt], bl[g][o], bl[g][o + 2]);
                    mma16816(acc[mt][nt], al[mt], bh[g][o], bh[g][o + 2]);
                }
        }
        __syncthreads();
    }

    // epilogue: c-frag -> Y
    const int gid = lid >> 2, t4 = lid & 3;
#pragma unroll
    for (int mt = 0; mt < 4; mt++) {
        int row0 = brow + wm * 64 + mt * 16 + gid;
#pragma unroll
        for (int nt = 0; nt < 4; nt++) {
            int col = bcol + wn * 32 + nt * 8 + t4 * 2;
            *(float2*)(Y + (size_t)row0 * N + col) =
                make_float2(acc[mt][nt][0], acc[mt][nt][1]);
            *(float2*)(Y + (size_t)(row0 + 8) * N + col) =
                make_float2(acc[mt][nt][2], acc[mt][nt][3]);
        }
    }
}

// ---------------- causal flash attention (unchanged) ----------------
#define FA_PAD 65
#define FA_SMEM (4 * 64 * FA_PAD * sizeof(float))

__global__ __launch_bounds__(256) void flash_attn(
    const float* __restrict__ Qp, const float* __restrict__ Kp,
    const float* __restrict__ Vp, float* __restrict__ Ctx)
{
    extern __shared__ float fsmem[];
    float (*Qs)[FA_PAD] = (float (*)[FA_PAD])(fsmem);
    float (*Ks)[FA_PAD] = (float (*)[FA_PAD])(fsmem + 64 * FA_PAD);
    float (*Vs)[FA_PAD] = (float (*)[FA_PAD])(fsmem + 2 * 64 * FA_PAD);
    float (*Ps)[FA_PAD] = (float (*)[FA_PAD])(fsmem + 3 * 64 * FA_PAD);

    const int qi = blockIdx.x;
    const int h  = blockIdx.y;
    const int b  = blockIdx.z;
    const int q0 = qi * 64;

    const int tid = threadIdx.x;
    const int ty = tid >> 4, tx = tid & 15;
    const int rbase = ty * 4, cbase = tx * 4;

    const float scale = 0.125f;
    const size_t base = (size_t)b * SEQ * DM + (size_t)h * DK;

    for (int i = tid; i < 64 * 16; i += 256) {
        int r = i >> 4, c4 = (i & 15) * 4;
        float4 qv = *(const float4*)(Qp + base + (size_t)(q0 + r) * DM + c4);
        Qs[r][c4 + 0] = qv.x; Qs[r][c4 + 1] = qv.y;
        Qs[r][c4 + 2] = qv.z; Qs[r][c4 + 3] = qv.w;
    }

    float m_i[4], l_i[4], acc[4][4];
#pragma unroll
    for (int i = 0; i < 4; i++) {
        m_i[i] = -1e30f; l_i[i] = 0.0f;
#pragma unroll
        for (int j = 0; j < 4; j++) acc[i][j] = 0.0f;
    }

    for (int jt = 0; jt <= qi; jt++) {
        const int k0 = jt * 64;
        __syncthreads();
        for (int i = tid; i < 64 * 16; i += 256) {
            int r = i >> 4, c4 = (i & 15) * 4;
            float4 kv = *(const float4*)(Kp + base + (size_t)(k0 + r) * DM + c4);
            Ks[r][c4 + 0] = kv.x; Ks[r][c4 + 1] = kv.y;
            Ks[r][c4 + 2] = kv.z; Ks[r][c4 + 3] = kv.w;
            float4 vv = *(const float4*)(Vp + base + (size_t)(k0 + r) * DM + c4);
            Vs[r][c4 + 0] = vv.x; Vs[r][c4 + 1] = vv.y;
            Vs[r][c4 + 2] = vv.z; Vs[r][c4 + 3] = vv.w;
        }
        __syncthreads();

        float s[4][4];
#pragma unroll
        for (int i = 0; i < 4; i++)
#pragma unroll
            for (int j = 0; j < 4; j++) s[i][j] = 0.0f;

#pragma unroll 8
        for (int d = 0; d < 64; d++) {
            float af[4], bf[4];
#pragma unroll
            for (int i = 0; i < 4; i++) af[i] = Qs[rbase + i][d];
#pragma unroll
            for (int j = 0; j < 4; j++) bf[j] = Ks[cbase + j][d];
#pragma unroll
            for (int i = 0; i < 4; i++)
#pragma unroll
                for (int j = 0; j < 4; j++)
                    s[i][j] = fmaf(af[i], bf[j], s[i][j]);
        }

        const bool diag = (jt == qi);
#pragma unroll
        for (int i = 0; i < 4; i++)
#pragma unroll
            for (int j = 0; j < 4; j++) {
                s[i][j] *= scale;
                if (diag && (k0 + cbase + j) > (q0 + rbase + i)) s[i][j] = -1e30f;
            }

        float alpha[4];
#pragma unroll
        for (int i = 0; i < 4; i++) {
            float ml = fmaxf(fmaxf(s[i][0], s[i][1]), fmaxf(s[i][2], s[i][3]));
#pragma unroll
            for (int off = 8; off >= 1; off >>= 1)
                ml = fmaxf(ml, __shfl_xor_sync(0xffffffffu, ml, off));
            float mn = fmaxf(m_i[i], ml);
            alpha[i] = __expf(m_i[i] - mn);
            float rs = 0.0f;
#pragma unroll
            for (int j = 0; j < 4; j++) {
                float p = __expf(s[i][j] - mn);
                Ps[rbase + i][cbase + j] = p;
                rs += p;
            }
#pragma unroll
            for (int off = 8; off >= 1; off >>= 1)
                rs += __shfl_xor_sync(0xffffffffu, rs, off);
            l_i[i] = l_i[i] * alpha[i] + rs;
            m_i[i] = mn;
        }
        __syncthreads();

#pragma unroll
        for (int i = 0; i < 4; i++)
#pragma unroll
            for (int j = 0; j < 4; j++) acc[i][j] *= alpha[i];

#pragma unroll 8
        for (int c = 0; c < 64; c++) {
            float pf[4], vf[4];
#pragma unroll
            for (int i = 0; i < 4; i++) pf[i] = Ps[rbase + i][c];
#pragma unroll
            for (int j = 0; j < 4; j++) vf[j] = Vs[c][cbase + j];
#pragma unroll
            for (int i = 0; i < 4; i++)
#pragma unroll
                for (int j = 0; j < 4; j++)
                    acc[i][j] = fmaf(pf[i], vf[j], acc[i][j]);
        }
    }

#pragma unroll
    for (int i = 0; i < 4; i++) {
        float inv_l = 1.0f / l_i[i];
#pragma unroll
        for (int j = 0; j < 4; j++)
            Ctx[base + (size_t)(q0 + rbase + i) * DM + cbase + j] = acc[i][j] * inv_l;
    }
}

// ---------------- launch ----------------
extern "C" void kernel_launch(void* const* d_in, const int* in_sizes, int n_in,
                              void* d_out, int out_size)
{
    const float* q  = (const float*)d_in[0];
    const float* k  = (const float*)d_in[1];
    const float* v  = (const float*)d_in[2];
    const float* Wq = (const float*)d_in[4];
    const float* Wk = (const float*)d_in[5];
    const float* Wv = (const float*)d_in[6];
    const float* Wo = (const float*)d_in[7];
    float* out = (float*)d_out;

    float *qp, *kp, *vp, *ctx;
    __nv_bfloat16 *ahi, *alo, *bhi, *blo;
    cudaGetSymbolAddress((void**)&qp,  g_qproj);
    cudaGetSymbolAddress((void**)&kp,  g_kproj);
    cudaGetSymbolAddress((void**)&vp,  g_vproj);
    cudaGetSymbolAddress((void**)&ctx, g_ctx);
    cudaGetSymbolAddress((void**)&ahi, g_ahi);
    cudaGetSymbolAddress((void**)&alo, g_alo);
    cudaGetSymbolAddress((void**)&bhi, g_bhi);
    cudaGetSymbolAddress((void**)&blo, g_blo);

    cudaFuncSetAttribute(gemm_bf16x3, cudaFuncAttributeMaxDynamicSharedMemorySize,
                         GEMM_SMEM);
    cudaFuncSetAttribute(flash_attn, cudaFuncAttributeMaxDynamicSharedMemorySize,
                         (int)FA_SMEM);

    const int NA4 = MTOT * DM / 4;
    const int NW4 = DM * DM / 4;
    dim3 gg(DM / 128, MTOT / 128);   // (8, 64)

    cvt_split<<<NA4 / 256, 256>>>(q, ahi, alo, NA4);
    cvt_split<<<NW4 / 256, 256>>>(Wq, bhi, blo, NW4);
    gemm_bf16x3<<<gg, 256, GEMM_SMEM>>>(ahi, alo, bhi, blo, qp);

    cvt_split<<<NA4 / 256, 256>>>(k, ahi, alo, NA4);
    cvt_split<<<NW4 / 256, 256>>>(Wk, bhi, blo, NW4);
    gemm_bf16x3<<<gg, 256, GEMM_SMEM>>>(ahi, alo, bhi, blo, kp);

    cvt_split<<<NA4 / 256, 256>>>(v, ahi, alo, NA4);
    cvt_split<<<NW4 / 256, 256>>>(Wv, bhi, blo, NW4);
    gemm_bf16x3<<<gg, 256, GEMM_SMEM>>>(ahi, alo, bhi, blo, vp);

    flash_attn<<<dim3(SEQ / 64, NHEAD, BATCH), 256, FA_SMEM>>>(qp, kp, vp, ctx);

    cvt_split<<<NA4 / 256, 256>>>(ctx, ahi, alo, NA4);
    cvt_split<<<NW4 / 256, 256>>>(Wo, bhi, blo, NW4);
    gemm_bf16x3<<<gg, 256, GEMM_SMEM>>>(ahi, alo, bhi, blo, out);
}

// round 4
// speedup vs baseline: 2.6940x; 1.7203x over previous
#include <cuda_runtime.h>
#include <cuda_bf16.h>
#include <cstdint>

#define BATCH 4
#define SEQ   2048
#define DM    1024
#define NHEAD 16
#define DK    64
#define MTOT  (BATCH * SEQ)   // 8192

// ---------------- scratch (no allocations allowed) ----------------
__device__ __align__(16) __nv_bfloat16 g_ahi[MTOT * DM];
__device__ __align__(16) __nv_bfloat16 g_alo[MTOT * DM];
__device__ __align__(16) __nv_bfloat16 g_bhi[DM * DM];
__device__ __align__(16) __nv_bfloat16 g_blo[DM * DM];
__device__ __align__(16) __nv_bfloat16 g_qhi[MTOT * DM];
__device__ __align__(16) __nv_bfloat16 g_qlo[MTOT * DM];
__device__ __align__(16) __nv_bfloat16 g_khi[MTOT * DM];
__device__ __align__(16) __nv_bfloat16 g_klo[MTOT * DM];
__device__ __align__(16) __nv_bfloat16 g_vhi[MTOT * DM];
__device__ __align__(16) __nv_bfloat16 g_vlo[MTOT * DM];

// ---------------- PTX helpers (base sm_103 ISA only) ----------------
__device__ __forceinline__ uint32_t smem_u32(const void* p) {
    uint32_t a;
    asm("{ .reg .u64 t; cvta.to.shared.u64 t, %1; cvt.u32.u64 %0, t; }"
        : "=r"(a) : "l"(p));
    return a;
}

__device__ __forceinline__ void cp16(uint32_t dst, const void* src) {
    asm volatile("cp.async.cg.shared.global [%0], [%1], 16;"
                 :: "r"(dst), "l"(src));
}

__device__ __forceinline__ void ldsm4(uint32_t& r0, uint32_t& r1,
                                      uint32_t& r2, uint32_t& r3, uint32_t addr) {
    asm volatile("ldmatrix.sync.aligned.m8n8.x4.shared.b16 {%0,%1,%2,%3}, [%4];"
                 : "=r"(r0), "=r"(r1), "=r"(r2), "=r"(r3) : "r"(addr));
}

__device__ __forceinline__ void ldsm4t(uint32_t& r0, uint32_t& r1,
                                       uint32_t& r2, uint32_t& r3, uint32_t addr) {
    asm volatile("ldmatrix.sync.aligned.m8n8.x4.trans.shared.b16 {%0,%1,%2,%3}, [%4];"
                 : "=r"(r0), "=r"(r1), "=r"(r2), "=r"(r3) : "r"(addr));
}

__device__ __forceinline__ void mma16816(float* c, const uint32_t* a,
                                         uint32_t b0, uint32_t b1) {
    asm volatile(
        "mma.sync.aligned.m16n8k16.row.col.f32.bf16.bf16.f32 "
        "{%0,%1,%2,%3}, {%4,%5,%6,%7}, {%8,%9}, {%0,%1,%2,%3};"
        : "+f"(c[0]), "+f"(c[1]), "+f"(c[2]), "+f"(c[3])
        : "r"(a[0]), "r"(a[1]), "r"(a[2]), "r"(a[3]), "r"(b0), "r"(b1));
}

__device__ __forceinline__ float ex2f(float x) {
    float y;
    asm("ex2.approx.f32 %0, %1;" : "=f"(y) : "f"(x));
    return y;
}

// split (v0,v1) -> packed bf16x2 hi (truncated) + bf16x2 lo (RNE residual)
__device__ __forceinline__ void pack_hl(float v0, float v1,
                                        uint32_t& hi, uint32_t& lo) {
    uint32_t u0 = __float_as_uint(v0), u1 = __float_as_uint(v1);
    hi = __byte_perm(u0, u1, 0x7632);
    float r0 = v0 - __uint_as_float(u0 & 0xffff0000u);
    float r1 = v1 - __uint_as_float(u1 & 0xffff0000u);
    asm("cvt.rn.bf16x2.f32 %0, %1, %2;" : "=r"(lo) : "f"(r1), "f"(r0));
}

// ---------------- fp32 -> bf16 hi/lo split ----------------
__global__ __launch_bounds__(256) void cvt_split(
    const float* __restrict__ x, __nv_bfloat16* __restrict__ hi,
    __nv_bfloat16* __restrict__ lo, int n4)
{
    int i = blockIdx.x * 256 + threadIdx.x;
    if (i >= n4) return;
    float4 v = ((const float4*)x)[i];
    uint32_t h0, l0, h1, l1;
    pack_hl(v.x, v.y, h0, l0);
    pack_hl(v.z, v.w, h1, l1);
    uint32_t* hp = (uint32_t*)hi;
    uint32_t* lp = (uint32_t*)lo;
    hp[2 * i] = h0; hp[2 * i + 1] = h1;
    lp[2 * i] = l0; lp[2 * i + 1] = l1;
}

// ---------------- mma.sync GEMM: Y = A @ B^T, bf16x3 ----------------
#define BK        32
#define ROW_BF16  40
#define ROW_B     (ROW_BF16 * 2)         // 80 bytes
#define MAT_B     (128 * ROW_B)          // 10240
#define STAGE_B   (4 * MAT_B)
#define GEMM_SMEM (2 * STAGE_B)          // 81920

__global__ __launch_bounds__(256, 1)
void gemm_bf16x3(const __nv_bfloat16* __restrict__ Ahi,
                 const __nv_bfloat16* __restrict__ Alo,
                 const __nv_bfloat16* __restrict__ Bhi,
                 const __nv_bfloat16* __restrict__ Blo,
                 float* __restrict__ Y,
                 __nv_bfloat16* __restrict__ Yhi,
                 __nv_bfloat16* __restrict__ Ylo,
                 int split)
{
    extern __shared__ __align__(128) char smem[];
    const int K = 1024, N = 1024;
    const int tid = threadIdx.x;
    const int w   = tid >> 5, lid = tid & 31;
    const int wm  = w >> 2,  wn  = w & 3;
    const int brow = blockIdx.y * 128, bcol = blockIdx.x * 128;
    const uint32_t sb = smem_u32(smem);

    const __nv_bfloat16* src[4] = {
        Ahi + (size_t)brow * K, Alo + (size_t)brow * K,
        Bhi + (size_t)bcol * K, Blo + (size_t)bcol * K };

    const uint32_t lrow = lid & 15;
    const uint32_t lcol = (lid >> 4) * 16;

    auto load_stage = [&](int s) {
        const uint32_t base = sb + (s & 1) * STAGE_B;
        const int k0 = s * BK;
#pragma unroll
        for (int t = 0; t < 8; t++) {
            int i = tid + t * 256;
            int m = i >> 9;
            int rem = i & 511;
            int r = rem >> 2, c = rem & 3;
            cp16(base + m * MAT_B + r * ROW_B + c * 16,
                 src[m] + k0 + (size_t)r * K + c * 8);
        }
        asm volatile("cp.async.commit_group;" ::: "memory");
    };

    float acc[4][4][4];
#pragma unroll
    for (int mt = 0; mt < 4; mt++)
#pragma unroll
        for (int nt = 0; nt < 4; nt++)
#pragma unroll
            for (int r = 0; r < 4; r++) acc[mt][nt][r] = 0.0f;

    load_stage(0);

    for (int s = 0; s < 32; s++) {
        if (s + 1 < 32) {
            load_stage(s + 1);
            asm volatile("cp.async.wait_group 1;" ::: "memory");
        } else {
            asm volatile("cp.async.wait_group 0;" ::: "memory");
        }
        __syncthreads();

        const uint32_t base = sb + (s & 1) * STAGE_B;
        const uint32_t ah_base = base;
        const uint32_t al_base = base + MAT_B;
        const uint32_t bh_base = base + 2 * MAT_B;
        const uint32_t bl_base = base + 3 * MAT_B;

#pragma unroll
        for (int ks = 0; ks < 2; ks++) {
            const uint32_t kb = ks * 32 + lcol;
            uint32_t ah[4][4], al[4][4], bh[2][4], bl[2][4];
#pragma unroll
            for (int mt = 0; mt < 4; mt++) {
                uint32_t ra = (wm * 64 + mt * 16 + lrow) * ROW_B + kb;
                ldsm4(ah[mt][0], ah[mt][1], ah[mt][2], ah[mt][3], ah_base + ra);
                ldsm4(al[mt][0], al[mt][1], al[mt][2], al[mt][3], al_base + ra);
            }
#pragma unroll
            for (int g = 0; g < 2; g++) {
                uint32_t rb = (wn * 32 + g * 16 + lrow) * ROW_B + kb;
                ldsm4(bh[g][0], bh[g][1], bh[g][2], bh[g][3], bh_base + rb);
                ldsm4(bl[g][0], bl[g][1], bl[g][2], bl[g][3], bl_base + rb);
            }
#pragma unroll
            for (int mt = 0; mt < 4; mt++)
#pragma unroll
                for (int nt = 0; nt < 4; nt++) {
                    const int g = nt >> 1, o = nt & 1;
                    mma16816(acc[mt][nt], ah[mt], bh[g][o], bh[g][o + 2]);
                    mma16816(acc[mt][nt], ah[mt], bl[g][o], bl[g][o + 2]);
                    mma16816(acc[mt][nt], al[mt], bh[g][o], bh[g][o + 2]);
                }
        }
        __syncthreads();
    }

    const int gid = lid >> 2, t4 = lid & 3;
#pragma unroll
    for (int mt = 0; mt < 4; mt++) {
        int row0 = brow + wm * 64 + mt * 16 + gid;
#pragma unroll
        for (int nt = 0; nt < 4; nt++) {
            int col = bcol + wn * 32 + nt * 8 + t4 * 2;
            if (split) {
                uint32_t hh, ll;
                pack_hl(acc[mt][nt][0], acc[mt][nt][1], hh, ll);
                *(uint32_t*)&Yhi[(size_t)row0 * N + col] = hh;
                *(uint32_t*)&Ylo[(size_t)row0 * N + col] = ll;
                pack_hl(acc[mt][nt][2], acc[mt][nt][3], hh, ll);
                *(uint32_t*)&Yhi[(size_t)(row0 + 8) * N + col] = hh;
                *(uint32_t*)&Ylo[(size_t)(row0 + 8) * N + col] = ll;
            } else {
                *(float2*)(Y + (size_t)row0 * N + col) =
                    make_float2(acc[mt][nt][0], acc[mt][nt][1]);
                *(float2*)(Y + (size_t)(row0 + 8) * N + col) =
                    make_float2(acc[mt][nt][2], acc[mt][nt][3]);
            }
        }
    }
}

// ---------------- tensor-core causal flash attention ----------------
// CTA: 128 q-rows for one (b,h). 8 warps x 16 rows. K/V tiles of 64.
#define AROWB  144                 // 64 bf16 = 128B + 16B pad
#define AMAT   (64 * AROWB)        // 9216
#define ASTAGE (4 * AMAT)          // Khi | Klo | Vhi | Vlo = 36864
#define AQ     (2 * 128 * AROWB)   // Qhi | Qlo = 36864
#define FA_SMEM (AQ + 2 * ASTAGE)  // 110592

__global__ __launch_bounds__(256, 1)
void flash_attn_mma(
    const __nv_bfloat16* __restrict__ Qhi, const __nv_bfloat16* __restrict__ Qlo,
    const __nv_bfloat16* __restrict__ Khi, const __nv_bfloat16* __restrict__ Klo,
    const __nv_bfloat16* __restrict__ Vhi, const __nv_bfloat16* __restrict__ Vlo,
    __nv_bfloat16* __restrict__ Chi, __nv_bfloat16* __restrict__ Clo)
{
    extern __shared__ __align__(128) char smem[];
    const int tid = threadIdx.x, w = tid >> 5, lid = tid & 31;
    const int gid = lid >> 2, t4 = lid & 3;
    const int qi = (SEQ / 128 - 1) - blockIdx.x;   // big tiles first
    const int h = blockIdx.y, b = blockIdx.z;
    const int q0 = qi * 128;
    const int nt = 2 * qi + 2;
    const uint32_t sb = smem_u32(smem);
    const size_t gb = (size_t)b * SEQ * DM + (size_t)h * DK;

    // ---- Q -> smem (async group 0): 128 rows x 8 chunks x {hi,lo}
#pragma unroll
    for (int t = 0; t < 8; t++) {
        int i = tid + t * 256;
        int mt = i >> 10, rem = i & 1023, r = rem >> 3, c = rem & 7;
        const __nv_bfloat16* s = (mt ? Qlo : Qhi) + gb + (size_t)(q0 + r) * DM + c * 8;
        cp16(sb + mt * (128 * AROWB) + r * AROWB + c * 16, s);
    }
    asm volatile("cp.async.commit_group;" ::: "memory");

    auto load_kv = [&](int jt, int buf) {
        const uint32_t st = sb + AQ + buf * ASTAGE;
        const int k0 = jt * 64;
#pragma unroll
        for (int t = 0; t < 8; t++) {
            int i = tid + t * 256;
            int mt = i >> 9, rem = i & 511, r = rem >> 3, c = rem & 7;
            const __nv_bfloat16* s;
            if (mt == 0) s = Khi; else if (mt == 1) s = Klo;
            else if (mt == 2) s = Vhi; else s = Vlo;
            cp16(st + mt * AMAT + r * AROWB + c * 16,
                 s + gb + (size_t)(k0 + r) * DM + c * 8);
        }
        asm volatile("cp.async.commit_group;" ::: "memory");
    };

    load_kv(0, 0);

    float Oa[8][4];
    float m0 = -1e30f, m1 = -1e30f, l0 = 0.f, l1 = 0.f;
#pragma unroll
    for (int nf = 0; nf < 8; nf++)
#pragma unroll
        for (int c = 0; c < 4; c++) Oa[nf][c] = 0.f;

    const float SC = 0.18033688011112042f;   // 0.125 * log2(e)
    const uint32_t qaddr = sb + (w * 16 + (lid & 15)) * AROWB + ((lid >> 4) << 4);
    const uint32_t lrowoff = (((lid >> 3) & 1) * 8 + (lid & 7)) * AROWB + ((lid >> 4) << 4);

    for (int jt = 0; jt < nt; jt++) {
        if (jt + 1 < nt) {
            load_kv(jt + 1, (jt + 1) & 1);
            asm volatile("cp.async.wait_group 1;" ::: "memory");
        } else {
            asm volatile("cp.async.wait_group 0;" ::: "memory");
        }
        __syncthreads();

        const uint32_t st = sb + AQ + (jt & 1) * ASTAGE;
        const int k0 = jt * 64;

        // Q frags (from resident smem)
        uint32_t qh[4][4], ql[4][4];
#pragma unroll
        for (int ks = 0; ks < 4; ks++) {
            ldsm4(qh[ks][0], qh[ks][1], qh[ks][2], qh[ks][3], qaddr + ks * 32);
            ldsm4(ql[ks][0], ql[ks][1], ql[ks][2], ql[ks][3],
                  qaddr + 128 * AROWB + ks * 32);
        }

        // ---- S = Q K^T (bf16x3)
        float S[8][4];
#pragma unroll
        for (int nf = 0; nf < 8; nf++)
#pragma unroll
            for (int c = 0; c < 4; c++) S[nf][c] = 0.f;

#pragma unroll
        for (int g = 0; g < 4; g++) {
            uint32_t kh[4][4], kl[4][4];
#pragma unroll
            for (int ks = 0; ks < 4; ks++) {
                uint32_t ka = st + g * (16 * AROWB) + lrowoff + ks * 32;
                ldsm4(kh[ks][0], kh[ks][1], kh[ks][2], kh[ks][3], ka);
                ldsm4(kl[ks][0], kl[ks][1], kl[ks][2], kl[ks][3], ka + AMAT);
            }
#pragma unroll
            for (int ks = 0; ks < 4; ks++)
#pragma unroll
                for (int o = 0; o < 2; o++) {
                    mma16816(S[2 * g + o], qh[ks], kh[ks][o], kh[ks][o + 2]);
                    mma16816(S[2 * g + o], qh[ks], kl[ks][o], kl[ks][o + 2]);
                    mma16816(S[2 * g + o], ql[ks], kh[ks][o], kh[ks][o + 2]);
                }
        }

        // ---- softmax (base-2 domain)
        const bool diag = (jt >= nt - 2);
        const int row0 = q0 + w * 16 + gid;
#pragma unroll
        for (int nf = 0; nf < 8; nf++) {
            int coln = k0 + nf * 8 + 2 * t4;
            S[nf][0] *= SC; S[nf][1] *= SC; S[nf][2] *= SC; S[nf][3] *= SC;
            if (diag) {
                if (coln     > row0)     S[nf][0] = -1e30f;
                if (coln + 1 > row0)     S[nf][1] = -1e30f;
                if (coln     > row0 + 8) S[nf][2] = -1e30f;
                if (coln + 1 > row0 + 8) S[nf][3] = -1e30f;
            }
        }
        float mx0 = -1e30f, mx1 = -1e30f;
#pragma unroll
        for (int nf = 0; nf < 8; nf++) {
            mx0 = fmaxf(mx0, fmaxf(S[nf][0], S[nf][1]));
            mx1 = fmaxf(mx1, fmaxf(S[nf][2], S[nf][3]));
        }
        mx0 = fmaxf(mx0, __shfl_xor_sync(0xffffffffu, mx0, 1));
        mx0 = fmaxf(mx0, __shfl_xor_sync(0xffffffffu, mx0, 2));
        mx1 = fmaxf(mx1, __shfl_xor_sync(0xffffffffu, mx1, 1));
        mx1 = fmaxf(mx1, __shfl_xor_sync(0xffffffffu, mx1, 2));

        float m0n = fmaxf(m0, mx0), m1n = fmaxf(m1, mx1);
        float a0 = ex2f(m0 - m0n), a1 = ex2f(m1 - m1n);
        m0 = m0n; m1 = m1n;

        float rs0 = 0.f, rs1 = 0.f;
        uint32_t phi[4][4], plo[4][4];
#pragma unroll
        for (int ks = 0; ks < 4; ks++)
#pragma unroll
            for (int half = 0; half < 2; half++) {
                int nf = 2 * ks + half;
                float p0 = ex2f(S[nf][0] - m0n);
                float p1 = ex2f(S[nf][1] - m0n);
                float p2 = ex2f(S[nf][2] - m1n);
                float p3 = ex2f(S[nf][3] - m1n);
                rs0 += p0 + p1; rs1 += p2 + p3;
                pack_hl(p0, p1, phi[ks][2 * half],     plo[ks][2 * half]);
                pack_hl(p2, p3, phi[ks][2 * half + 1], plo[ks][2 * half + 1]);
            }
        rs0 += __shfl_xor_sync(0xffffffffu, rs0, 1);
        rs0 += __shfl_xor_sync(0xffffffffu, rs0, 2);
        rs1 += __shfl_xor_sync(0xffffffffu, rs1, 1);
        rs1 += __shfl_xor_sync(0xffffffffu, rs1, 2);
        l0 = l0 * a0 + rs0;
        l1 = l1 * a1 + rs1;
#pragma unroll
        for (int nf = 0; nf < 8; nf++) {
            Oa[nf][0] *= a0; Oa[nf][1] *= a0;
            Oa[nf][2] *= a1; Oa[nf][3] *= a1;
        }

        // ---- O += P V (bf16x3), V^T frags via ldmatrix.trans
#pragma unroll
        for (int g = 0; g < 4; g++) {
            uint32_t vh[4][4], vl[4][4];
#pragma unroll
            for (int ks = 0; ks < 4; ks++) {
                uint32_t va = st + 2 * AMAT + ks * (16 * AROWB) + lrowoff + g * 32;
                ldsm4t(vh[ks][0], vh[ks][1], vh[ks][2], vh[ks][3], va);
                ldsm4t(vl[ks][0], vl[ks][1], vl[ks][2], vl[ks][3], va + AMAT);
            }
#pragma unroll
            for (int ks = 0; ks < 4; ks++)
#pragma unroll
                for (int o = 0; o < 2; o++) {
                    mma16816(Oa[2 * g + o], phi[ks], vh[ks][2 * o], vh[ks][2 * o + 1]);
                    mma16816(Oa[2 * g + o], phi[ks], vl[ks][2 * o], vl[ks][2 * o + 1]);
                    mma16816(Oa[2 * g + o], plo[ks], vh[ks][2 * o], vh[ks][2 * o + 1]);
                }
        }
        __syncthreads();
    }

    // ---- epilogue: ctx = O / l, written as bf16 hi/lo
    float il0 = 1.f / l0, il1 = 1.f / l1;
    const int row0 = q0 + w * 16 + gid;
#pragma unroll
    for (int nf = 0; nf < 8; nf++) {
        int col = nf * 8 + 2 * t4;
        size_t ad0 = gb + (size_t)row0 * DM + col;
        size_t ad1 = gb + (size_t)(row0 + 8) * DM + col;
        uint32_t hh, ll;
        pack_hl(Oa[nf][0] * il0, Oa[nf][1] * il0, hh, ll);
        *(uint32_t*)&Chi[ad0] = hh; *(uint32_t*)&Clo[ad0] = ll;
        pack_hl(Oa[nf][2] * il1, Oa[nf][3] * il1, hh, ll);
        *(uint32_t*)&Chi[ad1] = hh; *(uint32_t*)&Clo[ad1] = ll;
    }
}

// ---------------- launch ----------------
extern "C" void kernel_launch(void* const* d_in, const int* in_sizes, int n_in,
                              void* d_out, int out_size)
{
    const float* q  = (const float*)d_in[0];
    const float* k  = (const float*)d_in[1];
    const float* v  = (const float*)d_in[2];
    const float* Wq = (const float*)d_in[4];
    const float* Wk = (const float*)d_in[5];
    const float* Wv = (const float*)d_in[6];
    const float* Wo = (const float*)d_in[7];
    float* out = (float*)d_out;

    __nv_bfloat16 *ahi, *alo, *bhi, *blo;
    __nv_bfloat16 *qhi, *qlo, *khi, *klo, *vhi, *vlo;
    cudaGetSymbolAddress((void**)&ahi, g_ahi);
    cudaGetSymbolAddress((void**)&alo, g_alo);
    cudaGetSymbolAddress((void**)&bhi, g_bhi);
    cudaGetSymbolAddress((void**)&blo, g_blo);
    cudaGetSymbolAddress((void**)&qhi, g_qhi);
    cudaGetSymbolAddress((void**)&qlo, g_qlo);
    cudaGetSymbolAddress((void**)&khi, g_khi);
    cudaGetSymbolAddress((void**)&klo, g_klo);
    cudaGetSymbolAddress((void**)&vhi, g_vhi);
    cudaGetSymbolAddress((void**)&vlo, g_vlo);

    cudaFuncSetAttribute(gemm_bf16x3, cudaFuncAttributeMaxDynamicSharedMemorySize,
                         GEMM_SMEM);
    cudaFuncSetAttribute(flash_attn_mma, cudaFuncAttributeMaxDynamicSharedMemorySize,
                         FA_SMEM);

    const int NA4 = MTOT * DM / 4;
    const int NW4 = DM * DM / 4;
    dim3 gg(DM / 128, MTOT / 128);   // (8, 64)

    // Q/K/V projections -> bf16 hi/lo directly
    cvt_split<<<NA4 / 256, 256>>>(q, ahi, alo, NA4);
    cvt_split<<<NW4 / 256, 256>>>(Wq, bhi, blo, NW4);
    gemm_bf16x3<<<gg, 256, GEMM_SMEM>>>(ahi, alo, bhi, blo, nullptr, qhi, qlo, 1);

    cvt_split<<<NA4 / 256, 256>>>(k, ahi, alo, NA4);
    cvt_split<<<NW4 / 256, 256>>>(Wk, bhi, blo, NW4);
    gemm_bf16x3<<<gg, 256, GEMM_SMEM>>>(ahi, alo, bhi, blo, nullptr, khi, klo, 1);

    cvt_split<<<NA4 / 256, 256>>>(v, ahi, alo, NA4);
    cvt_split<<<NW4 / 256, 256>>>(Wv, bhi, blo, NW4);
    gemm_bf16x3<<<gg, 256, GEMM_SMEM>>>(ahi, alo, bhi, blo, nullptr, vhi, vlo, 1);

    // attention writes ctx hi/lo into g_ahi/g_alo (A operand of final GEMM)
    flash_attn_mma<<<dim3(SEQ / 128, NHEAD, BATCH), 256, FA_SMEM>>>(
        qhi, qlo, khi, klo, vhi, vlo, ahi, alo);

    // output projection -> fp32 out
    cvt_split<<<NW4 / 256, 256>>>(Wo, bhi, blo, NW4);
    gemm_bf16x3<<<gg, 256, GEMM_SMEM>>>(ahi, alo, bhi, blo, out, nullptr, nullptr, 0);
}

// round 5
// speedup vs baseline: 2.7426x; 1.0181x over previous
#include <cuda_runtime.h>
#include <cuda_bf16.h>
#include <cstdint>

#define BATCH 4
#define SEQ   2048
#define DM    1024
#define NHEAD 16
#define DK    64
#define MTOT  (BATCH * SEQ)   // 8192
#define ADM   ((size_t)MTOT * DM)
#define WDM   ((size_t)DM * DM)

// ---------------- scratch (no allocations allowed) ----------------
__device__ __align__(16) __nv_bfloat16 g_axhi[3 * ADM];   // split activations q|k|v ; slot0 reused for ctx
__device__ __align__(16) __nv_bfloat16 g_axlo[3 * ADM];
__device__ __align__(16) __nv_bfloat16 g_whi[4 * WDM];    // Wq|Wk|Wv|Wo
__device__ __align__(16) __nv_bfloat16 g_wlo[4 * WDM];
__device__ __align__(16) __nv_bfloat16 g_pjhi[3 * ADM];   // proj outputs qh|kh|vh
__device__ __align__(16) __nv_bfloat16 g_pjlo[3 * ADM];

// ---------------- PTX helpers (base sm_103 ISA only) ----------------
__device__ __forceinline__ uint32_t smem_u32(const void* p) {
    uint32_t a;
    asm("{ .reg .u64 t; cvta.to.shared.u64 t, %1; cvt.u32.u64 %0, t; }"
        : "=r"(a) : "l"(p));
    return a;
}

__device__ __forceinline__ void cp16(uint32_t dst, const void* src) {
    asm volatile("cp.async.cg.shared.global [%0], [%1], 16;"
                 :: "r"(dst), "l"(src));
}

__device__ __forceinline__ void ldsm4(uint32_t& r0, uint32_t& r1,
                                      uint32_t& r2, uint32_t& r3, uint32_t addr) {
    asm volatile("ldmatrix.sync.aligned.m8n8.x4.shared.b16 {%0,%1,%2,%3}, [%4];"
                 : "=r"(r0), "=r"(r1), "=r"(r2), "=r"(r3) : "r"(addr));
}

__device__ __forceinline__ void ldsm4t(uint32_t& r0, uint32_t& r1,
                                       uint32_t& r2, uint32_t& r3, uint32_t addr) {
    asm volatile("ldmatrix.sync.aligned.m8n8.x4.trans.shared.b16 {%0,%1,%2,%3}, [%4];"
                 : "=r"(r0), "=r"(r1), "=r"(r2), "=r"(r3) : "r"(addr));
}

__device__ __forceinline__ void mma16816(float* c, const uint32_t* a,
                                         uint32_t b0, uint32_t b1) {
    asm volatile(
        "mma.sync.aligned.m16n8k16.row.col.f32.bf16.bf16.f32 "
        "{%0,%1,%2,%3}, {%4,%5,%6,%7}, {%8,%9}, {%0,%1,%2,%3};"
        : "+f"(c[0]), "+f"(c[1]), "+f"(c[2]), "+f"(c[3])
        : "r"(a[0]), "r"(a[1]), "r"(a[2]), "r"(a[3]), "r"(b0), "r"(b1));
}

__device__ __forceinline__ float ex2f(float x) {
    float y;
    asm("ex2.approx.f32 %0, %1;" : "=f"(y) : "f"(x));
    return y;
}

__device__ __forceinline__ void pack_hl(float v0, float v1,
                                        uint32_t& hi, uint32_t& lo) {
    uint32_t u0 = __float_as_uint(v0), u1 = __float_as_uint(v1);
    hi = __byte_perm(u0, u1, 0x7632);
    float r0 = v0 - __uint_as_float(u0 & 0xffff0000u);
    float r1 = v1 - __uint_as_float(u1 & 0xffff0000u);
    asm("cvt.rn.bf16x2.f32 %0, %1, %2;" : "=r"(lo) : "f"(r1), "f"(r0));
}

// ---------------- fp32 -> bf16 hi/lo split (batched) ----------------
__device__ __forceinline__ void split_one(const float* __restrict__ x,
                                          __nv_bfloat16* __restrict__ hi,
                                          __nv_bfloat16* __restrict__ lo, int i) {
    float4 v = ((const float4*)x)[i];
    uint32_t h0, l0, h1, l1;
    pack_hl(v.x, v.y, h0, l0);
    pack_hl(v.z, v.w, h1, l1);
    uint32_t* hp = (uint32_t*)hi;
    uint32_t* lp = (uint32_t*)lo;
    hp[2 * i] = h0; hp[2 * i + 1] = h1;
    lp[2 * i] = l0; lp[2 * i + 1] = l1;
}

__global__ __launch_bounds__(256) void cvt_split3(
    const float* __restrict__ x0, const float* __restrict__ x1,
    const float* __restrict__ x2,
    __nv_bfloat16* __restrict__ hi, __nv_bfloat16* __restrict__ lo, int n4)
{
    int i = blockIdx.x * 256 + threadIdx.x;
    if (i >= n4) return;
    int z = blockIdx.z;
    const float* x = (z == 0) ? x0 : (z == 1) ? x1 : x2;
    split_one(x, hi + (size_t)z * n4 * 4, lo + (size_t)z * n4 * 4, i);
}

__global__ __launch_bounds__(256) void cvt_split4(
    const float* __restrict__ x0, const float* __restrict__ x1,
    const float* __restrict__ x2, const float* __restrict__ x3,
    __nv_bfloat16* __restrict__ hi, __nv_bfloat16* __restrict__ lo, int n4)
{
    int i = blockIdx.x * 256 + threadIdx.x;
    if (i >= n4) return;
    int z = blockIdx.z;
    const float* x = (z == 0) ? x0 : (z == 1) ? x1 : (z == 2) ? x2 : x3;
    split_one(x, hi + (size_t)z * n4 * 4, lo + (size_t)z * n4 * 4, i);
}

// ---------------- mma.sync GEMM: Y = A @ B^T, bf16x3, 4-stage pipeline ----------------
#define BK        32
#define ROW_BF16  40
#define ROW_B     (ROW_BF16 * 2)         // 80 bytes
#define MAT_B     (128 * ROW_B)          // 10240
#define STAGE_B   (4 * MAT_B)            // 40960
#define NSTAGE    4
#define GEMM_SMEM (NSTAGE * STAGE_B)     // 163840

__global__ __launch_bounds__(256, 1)
void gemm_bf16x3(const __nv_bfloat16* __restrict__ Ahi,
                 const __nv_bfloat16* __restrict__ Alo,
                 const __nv_bfloat16* __restrict__ Bhi,
                 const __nv_bfloat16* __restrict__ Blo,
                 float* __restrict__ Y,
                 __nv_bfloat16* __restrict__ Yhi,
                 __nv_bfloat16* __restrict__ Ylo,
                 int split)
{
    extern __shared__ __align__(128) char smem[];
    const int K = 1024, N = 1024;
    const int tid = threadIdx.x;
    const int w   = tid >> 5, lid = tid & 31;
    const int wm  = w >> 2,  wn  = w & 3;
    const int z   = blockIdx.z;
    const int brow = blockIdx.y * 128, bcol = blockIdx.x * 128;
    const uint32_t sb = smem_u32(smem);

    const size_t za = (size_t)z * ADM, zw = (size_t)z * WDM;
    const __nv_bfloat16* src[4] = {
        Ahi + za + (size_t)brow * K, Alo + za + (size_t)brow * K,
        Bhi + zw + (size_t)bcol * K, Blo + zw + (size_t)bcol * K };

    const uint32_t lrow = lid & 15;
    const uint32_t lcol = (lid >> 4) * 16;

    auto load_stage = [&](int s) {
        const uint32_t base = sb + (s & (NSTAGE - 1)) * STAGE_B;
        const int k0 = s * BK;
#pragma unroll
        for (int t = 0; t < 8; t++) {
            int i = tid + t * 256;
            int m = i >> 9;
            int rem = i & 511;
            int r = rem >> 2, c = rem & 3;
            cp16(base + m * MAT_B + r * ROW_B + c * 16,
                 src[m] + k0 + (size_t)r * K + c * 8);
        }
        asm volatile("cp.async.commit_group;" ::: "memory");
    };

    float acc[4][4][4];
#pragma unroll
    for (int mt = 0; mt < 4; mt++)
#pragma unroll
        for (int nt = 0; nt < 4; nt++)
#pragma unroll
            for (int r = 0; r < 4; r++) acc[mt][nt][r] = 0.0f;

    load_stage(0);
    load_stage(1);
    load_stage(2);

#pragma unroll 1
    for (int s = 0; s < 32; s++) {
        asm volatile("cp.async.wait_group 2;" ::: "memory");
        __syncthreads();

        const uint32_t base = sb + (s & (NSTAGE - 1)) * STAGE_B;
        const uint32_t ah_base = base;
        const uint32_t al_base = base + MAT_B;
        const uint32_t bh_base = base + 2 * MAT_B;
        const uint32_t bl_base = base + 3 * MAT_B;

#pragma unroll
        for (int ks = 0; ks < 2; ks++) {
            const uint32_t kb = ks * 32 + lcol;
            uint32_t ah[4][4], al[4][4], bh[2][4], bl[2][4];
#pragma unroll
            for (int mt = 0; mt < 4; mt++) {
                uint32_t ra = (wm * 64 + mt * 16 + lrow) * ROW_B + kb;
                ldsm4(ah[mt][0], ah[mt][1], ah[mt][2], ah[mt][3], ah_base + ra);
                ldsm4(al[mt][0], al[mt][1], al[mt][2], al[mt][3], al_base + ra);
            }
#pragma unroll
            for (int g = 0; g < 2; g++) {
                uint32_t rb = (wn * 32 + g * 16 + lrow) * ROW_B + kb;
                ldsm4(bh[g][0], bh[g][1], bh[g][2], bh[g][3], bh_base + rb);
                ldsm4(bl[g][0], bl[g][1], bl[g][2], bl[g][3], bl_base + rb);
            }
#pragma unroll
            for (int mt = 0; mt < 4; mt++)
#pragma unroll
                for (int nt = 0; nt < 4; nt++) {
                    const int g = nt >> 1, o = nt & 1;
                    mma16816(acc[mt][nt], ah[mt], bh[g][o], bh[g][o + 2]);
                    mma16816(acc[mt][nt], ah[mt], bl[g][o], bl[g][o + 2]);
                    mma16816(acc[mt][nt], al[mt], bh[g][o], bh[g][o + 2]);
                }
        }

        if (s + 3 < 32) load_stage(s + 3);
        else asm volatile("cp.async.commit_group;" ::: "memory");
    }

    const int gid = lid >> 2, t4 = lid & 3;
#pragma unroll
    for (int mt = 0; mt < 4; mt++) {
        int row0 = brow + wm * 64 + mt * 16 + gid;
#pragma unroll
        for (int nt = 0; nt < 4; nt++) {
            int col = bcol + wn * 32 + nt * 8 + t4 * 2;
            if (split) {
                uint32_t hh, ll;
                pack_hl(acc[mt][nt][0], acc[mt][nt][1], hh, ll);
                *(uint32_t*)&Yhi[za + (size_t)row0 * N + col] = hh;
                *(uint32_t*)&Ylo[za + (size_t)row0 * N + col] = ll;
                pack_hl(acc[mt][nt][2], acc[mt][nt][3], hh, ll);
                *(uint32_t*)&Yhi[za + (size_t)(row0 + 8) * N + col] = hh;
                *(uint32_t*)&Ylo[za + (size_t)(row0 + 8) * N + col] = ll;
            } else {
                *(float2*)(Y + (size_t)row0 * N + col) =
                    make_float2(acc[mt][nt][0], acc[mt][nt][1]);
                *(float2*)(Y + (size_t)(row0 + 8) * N + col) =
                    make_float2(acc[mt][nt][2], acc[mt][nt][3]);
            }
        }
    }
}

// ---------------- tensor-core causal flash attention ----------------
#define AROWB  144
#define AMAT   (64 * AROWB)
#define ASTAGE (4 * AMAT)
#define AQ     (2 * 128 * AROWB)
#define FA_SMEM (AQ + 2 * ASTAGE)

__global__ __launch_bounds__(256, 1)
void flash_attn_mma(
    const __nv_bfloat16* __restrict__ Qhi, const __nv_bfloat16* __restrict__ Qlo,
    const __nv_bfloat16* __restrict__ Khi, const __nv_bfloat16* __restrict__ Klo,
    const __nv_bfloat16* __restrict__ Vhi, const __nv_bfloat16* __restrict__ Vlo,
    __nv_bfloat16* __restrict__ Chi, __nv_bfloat16* __restrict__ Clo)
{
    extern __shared__ __align__(128) char smem[];
    const int tid = threadIdx.x, w = tid >> 5, lid = tid & 31;
    const int gid = lid >> 2, t4 = lid & 3;
    const int qi = (SEQ / 128 - 1) - blockIdx.x;
    const int h = blockIdx.y, b = blockIdx.z;
    const int q0 = qi * 128;
    const int nt = 2 * qi + 2;
    const uint32_t sb = smem_u32(smem);
    const size_t gb = (size_t)b * SEQ * DM + (size_t)h * DK;

#pragma unroll
    for (int t = 0; t < 8; t++) {
        int i = tid + t * 256;
        int mt = i >> 10, rem = i & 1023, r = rem >> 3, c = rem & 7;
        const __nv_bfloat16* s = (mt ? Qlo : Qhi) + gb + (size_t)(q0 + r) * DM + c * 8;
        cp16(sb + mt * (128 * AROWB) + r * AROWB + c * 16, s);
    }
    asm volatile("cp.async.commit_group;" ::: "memory");

    auto load_kv = [&](int jt, int buf) {
        const uint32_t st = sb + AQ + buf * ASTAGE;
        const int k0 = jt * 64;
#pragma unroll
        for (int t = 0; t < 8; t++) {
            int i = tid + t * 256;
            int mt = i >> 9, rem = i & 511, r = rem >> 3, c = rem & 7;
            const __nv_bfloat16* s;
            if (mt == 0) s = Khi; else if (mt == 1) s = Klo;
            else if (mt == 2) s = Vhi; else s = Vlo;
            cp16(st + mt * AMAT + r * AROWB + c * 16,
                 s + gb + (size_t)(k0 + r) * DM + c * 8);
        }
        asm volatile("cp.async.commit_group;" ::: "memory");
    };

    load_kv(0, 0);

    float Oa[8][4];
    float m0 = -1e30f, m1 = -1e30f, l0 = 0.f, l1 = 0.f;
#pragma unroll
    for (int nf = 0; nf < 8; nf++)
#pragma unroll
        for (int c = 0; c < 4; c++) Oa[nf][c] = 0.f;

    const float SC = 0.18033688011112042f;   // 0.125 * log2(e)
    const uint32_t qaddr = sb + (w * 16 + (lid & 15)) * AROWB + ((lid >> 4) << 4);
    const uint32_t lrowoff = (((lid >> 3) & 1) * 8 + (lid & 7)) * AROWB + ((lid >> 4) << 4);

    for (int jt = 0; jt < nt; jt++) {
        if (jt + 1 < nt) {
            load_kv(jt + 1, (jt + 1) & 1);
            asm volatile("cp.async.wait_group 1;" ::: "memory");
        } else {
            asm volatile("cp.async.wait_group 0;" ::: "memory");
        }
        __syncthreads();

        const uint32_t st = sb + AQ + (jt & 1) * ASTAGE;
        const int k0 = jt * 64;

        uint32_t qh[4][4], ql[4][4];
#pragma unroll
        for (int ks = 0; ks < 4; ks++) {
            ldsm4(qh[ks][0], qh[ks][1], qh[ks][2], qh[ks][3], qaddr + ks * 32);
            ldsm4(ql[ks][0], ql[ks][1], ql[ks][2], ql[ks][3],
                  qaddr + 128 * AROWB + ks * 32);
        }

        float S[8][4];
#pragma unroll
        for (int nf = 0; nf < 8; nf++)
#pragma unroll
            for (int c = 0; c < 4; c++) S[nf][c] = 0.f;

#pragma unroll
        for (int g = 0; g < 4; g++) {
            uint32_t kh[4][4], kl[4][4];
#pragma unroll
            for (int ks = 0; ks < 4; ks++) {
                uint32_t ka = st + g * (16 * AROWB) + lrowoff + ks * 32;
                ldsm4(kh[ks][0], kh[ks][1], kh[ks][2], kh[ks][3], ka);
                ldsm4(kl[ks][0], kl[ks][1], kl[ks][2], kl[ks][3], ka + AMAT);
            }
#pragma unroll
            for (int ks = 0; ks < 4; ks++)
#pragma unroll
                for (int o = 0; o < 2; o++) {
                    mma16816(S[2 * g + o], qh[ks], kh[ks][o], kh[ks][o + 2]);
                    mma16816(S[2 * g + o], qh[ks], kl[ks][o], kl[ks][o + 2]);
                    mma16816(S[2 * g + o], ql[ks], kh[ks][o], kh[ks][o + 2]);
                }
        }

        const bool diag = (jt >= nt - 2);
        const int row0 = q0 + w * 16 + gid;
#pragma unroll
        for (int nf = 0; nf < 8; nf++) {
            int coln = k0 + nf * 8 + 2 * t4;
            S[nf][0] *= SC; S[nf][1] *= SC; S[nf][2] *= SC; S[nf][3] *= SC;
            if (diag) {
                if (coln     > row0)     S[nf][0] = -1e30f;
                if (coln + 1 > row0)     S[nf][1] = -1e30f;
                if (coln     > row0 + 8) S[nf][2] = -1e30f;
                if (coln + 1 > row0 + 8) S[nf][3] = -1e30f;
            }
        }
        float mx0 = -1e30f, mx1 = -1e30f;
#pragma unroll
        for (int nf = 0; nf < 8; nf++) {
            mx0 = fmaxf(mx0, fmaxf(S[nf][0], S[nf][1]));
            mx1 = fmaxf(mx1, fmaxf(S[nf][2], S[nf][3]));
        }
        mx0 = fmaxf(mx0, __shfl_xor_sync(0xffffffffu, mx0, 1));
        mx0 = fmaxf(mx0, __shfl_xor_sync(0xffffffffu, mx0, 2));
        mx1 = fmaxf(mx1, __shfl_xor_sync(0xffffffffu, mx1, 1));
        mx1 = fmaxf(mx1, __shfl_xor_sync(0xffffffffu, mx1, 2));

        float m0n = fmaxf(m0, mx0), m1n = fmaxf(m1, mx1);
        float a0 = ex2f(m0 - m0n), a1 = ex2f(m1 - m1n);
        m0 = m0n; m1 = m1n;

        float rs0 = 0.f, rs1 = 0.f;
        uint32_t phi[4][4], plo[4][4];
#pragma unroll
        for (int ks = 0; ks < 4; ks++)
#pragma unroll
            for (int half = 0; half < 2; half++) {
                int nf = 2 * ks + half;
                float p0 = ex2f(S[nf][0] - m0n);
                float p1 = ex2f(S[nf][1] - m0n);
                float p2 = ex2f(S[nf][2] - m1n);
                float p3 = ex2f(S[nf][3] - m1n);
                rs0 += p0 + p1; rs1 += p2 + p3;
                pack_hl(p0, p1, phi[ks][2 * half],     plo[ks][2 * half]);
                pack_hl(p2, p3, phi[ks][2 * half + 1], plo[ks][2 * half + 1]);
            }
        rs0 += __shfl_xor_sync(0xffffffffu, rs0, 1);
        rs0 += __shfl_xor_sync(0xffffffffu, rs0, 2);
        rs1 += __shfl_xor_sync(0xffffffffu, rs1, 1);
        rs1 += __shfl_xor_sync(0xffffffffu, rs1, 2);
        l0 = l0 * a0 + rs0;
        l1 = l1 * a1 + rs1;
#pragma unroll
        for (int nf = 0; nf < 8; nf++) {
            Oa[nf][0] *= a0; Oa[nf][1] *= a0;
            Oa[nf][2] *= a1; Oa[nf][3] *= a1;
        }

#pragma unroll
        for (int g = 0; g < 4; g++) {
            uint32_t vh[4][4], vl[4][4];
#pragma unroll
            for (int ks = 0; ks < 4; ks++) {
                uint32_t va = st + 2 * AMAT + ks * (16 * AROWB) + lrowoff + g * 32;
                ldsm4t(vh[ks][0], vh[ks][1], vh[ks][2], vh[ks][3], va);
                ldsm4t(vl[ks][0], vl[ks][1], vl[ks][2], vl[ks][3], va + AMAT);
            }
#pragma unroll
            for (int ks = 0; ks < 4; ks++)
#pragma unroll
                for (int o = 0; o < 2; o++) {
                    mma16816(Oa[2 * g + o], phi[ks], vh[ks][2 * o], vh[ks][2 * o + 1]);
                    mma16816(Oa[2 * g + o], phi[ks], vl[ks][2 * o], vl[ks][2 * o + 1]);
                    mma16816(Oa[2 * g + o], plo[ks], vh[ks][2 * o], vh[ks][2 * o + 1]);
                }
        }
        __syncthreads();
    }

    float il0 = 1.f / l0, il1 = 1.f / l1;
    const int row0 = q0 + w * 16 + gid;
#pragma unroll
    for (int nf = 0; nf < 8; nf++) {
        int col = nf * 8 + 2 * t4;
        size_t ad0 = gb + (size_t)row0 * DM + col;
        size_t ad1 = gb + (size_t)(row0 + 8) * DM + col;
        uint32_t hh, ll;
        pack_hl(Oa[nf][0] * il0, Oa[nf][1] * il0, hh, ll);
        *(uint32_t*)&Chi[ad0] = hh; *(uint32_t*)&Clo[ad0] = ll;
        pack_hl(Oa[nf][2] * il1, Oa[nf][3] * il1, hh, ll);
        *(uint32_t*)&Chi[ad1] = hh; *(uint32_t*)&Clo[ad1] = ll;
    }
}

// ---------------- launch ----------------
extern "C" void kernel_launch(void* const* d_in, const int* in_sizes, int n_in,
                              void* d_out, int out_size)
{
    const float* q  = (const float*)d_in[0];
    const float* k  = (const float*)d_in[1];
    const float* v  = (const float*)d_in[2];
    const float* Wq = (const float*)d_in[4];
    const float* Wk = (const float*)d_in[5];
    const float* Wv = (const float*)d_in[6];
    const float* Wo = (const float*)d_in[7];
    float* out = (float*)d_out;

    __nv_bfloat16 *axhi, *axlo, *whi, *wlo, *pjhi, *pjlo;
    cudaGetSymbolAddress((void**)&axhi, g_axhi);
    cudaGetSymbolAddress((void**)&axlo, g_axlo);
    cudaGetSymbolAddress((void**)&whi,  g_whi);
    cudaGetSymbolAddress((void**)&wlo,  g_wlo);
    cudaGetSymbolAddress((void**)&pjhi, g_pjhi);
    cudaGetSymbolAddress((void**)&pjlo, g_pjlo);

    cudaFuncSetAttribute(gemm_bf16x3, cudaFuncAttributeMaxDynamicSharedMemorySize,
                         GEMM_SMEM);
    cudaFuncSetAttribute(flash_attn_mma, cudaFuncAttributeMaxDynamicSharedMemorySize,
                         FA_SMEM);

    const int NA4 = (int)(ADM / 4);
    const int NW4 = (int)(WDM / 4);

    // split all activations and all weights (batched)
    cvt_split3<<<dim3(NA4 / 256, 1, 3), 256>>>(q, k, v, axhi, axlo, NA4);
    cvt_split4<<<dim3(NW4 / 256, 1, 4), 256>>>(Wq, Wk, Wv, Wo, whi, wlo, NW4);

    // Q/K/V projections in one batched launch -> bf16 hi/lo
    gemm_bf16x3<<<dim3(DM / 128, MTOT / 128, 3), 256, GEMM_SMEM>>>(
        axhi, axlo, whi, wlo, nullptr, pjhi, pjlo, 1);

    // attention writes ctx hi/lo into axhi/axlo slot 0 (A of final GEMM)
    flash_attn_mma<<<dim3(SEQ / 128, NHEAD, BATCH), 256, FA_SMEM>>>(
        pjhi, pjlo, pjhi + ADM, pjlo + ADM, pjhi + 2 * ADM, pjlo + 2 * ADM,
        axhi, axlo);

    // output projection (Wo is weight slot 3) -> fp32 out
    gemm_bf16x3<<<dim3(DM / 128, MTOT / 128, 1), 256, GEMM_SMEM>>>(
        axhi, axlo, whi + 3 * WDM, wlo + 3 * WDM, out, nullptr, nullptr, 0);
}

// round 6
// speedup vs baseline: 3.5148x; 1.2815x over previous
#include <cuda_runtime.h>
#include <cuda_bf16.h>
#include <cstdint>

#define BATCH 4
#define SEQ   2048
#define DM    1024
#define NHEAD 16
#define DK    64
#define MTOT  (BATCH * SEQ)   // 8192
#define ADM   ((size_t)MTOT * DM)

// ---------------- scratch (no allocations allowed) ----------------
__device__ __align__(16) __nv_bfloat16 g_pjhi[3 * ADM];   // proj outputs qh|kh|vh (hi)
__device__ __align__(16) __nv_bfloat16 g_pjlo[3 * ADM];   // (lo)
__device__ __align__(16) float         g_ctx [ADM];       // attention output (fp32)

// ---------------- PTX helpers (base sm_103 ISA only) ----------------
__device__ __forceinline__ uint32_t smem_u32(const void* p) {
    uint32_t a;
    asm("{ .reg .u64 t; cvta.to.shared.u64 t, %1; cvt.u32.u64 %0, t; }"
        : "=r"(a) : "l"(p));
    return a;
}

__device__ __forceinline__ void cp16(uint32_t dst, const void* src) {
    asm volatile("cp.async.cg.shared.global [%0], [%1], 16;"
                 :: "r"(dst), "l"(src));
}

__device__ __forceinline__ void ldsm4(uint32_t& r0, uint32_t& r1,
                                      uint32_t& r2, uint32_t& r3, uint32_t addr) {
    asm volatile("ldmatrix.sync.aligned.m8n8.x4.shared.b16 {%0,%1,%2,%3}, [%4];"
                 : "=r"(r0), "=r"(r1), "=r"(r2), "=r"(r3) : "r"(addr));
}

__device__ __forceinline__ void ldsm4t(uint32_t& r0, uint32_t& r1,
                                       uint32_t& r2, uint32_t& r3, uint32_t addr) {
    asm volatile("ldmatrix.sync.aligned.m8n8.x4.trans.shared.b16 {%0,%1,%2,%3}, [%4];"
                 : "=r"(r0), "=r"(r1), "=r"(r2), "=r"(r3) : "r"(addr));
}

__device__ __forceinline__ void mma16816(float* c, const uint32_t* a,
                                         uint32_t b0, uint32_t b1) {
    asm volatile(
        "mma.sync.aligned.m16n8k16.row.col.f32.bf16.bf16.f32 "
        "{%0,%1,%2,%3}, {%4,%5,%6,%7}, {%8,%9}, {%0,%1,%2,%3};"
        : "+f"(c[0]), "+f"(c[1]), "+f"(c[2]), "+f"(c[3])
        : "r"(a[0]), "r"(a[1]), "r"(a[2]), "r"(a[3]), "r"(b0), "r"(b1));
}

__device__ __forceinline__ void mma1688t(float* c, const uint32_t* a,
                                         uint32_t b0, uint32_t b1) {
    asm volatile(
        "mma.sync.aligned.m16n8k8.row.col.f32.tf32.tf32.f32 "
        "{%0,%1,%2,%3}, {%4,%5,%6,%7}, {%8,%9}, {%0,%1,%2,%3};"
        : "+f"(c[0]), "+f"(c[1]), "+f"(c[2]), "+f"(c[3])
        : "r"(a[0]), "r"(a[1]), "r"(a[2]), "r"(a[3]), "r"(b0), "r"(b1));
}

__device__ __forceinline__ uint32_t tf32r(float x) {
    uint32_t y;
    asm("cvt.rna.tf32.f32 %0, %1;" : "=r"(y) : "f"(x));
    return y;
}

__device__ __forceinline__ float ex2f(float x) {
    float y;
    asm("ex2.approx.f32 %0, %1;" : "=f"(y) : "f"(x));
    return y;
}

__device__ __forceinline__ void pack_hl(float v0, float v1,
                                        uint32_t& hi, uint32_t& lo) {
    uint32_t u0 = __float_as_uint(v0), u1 = __float_as_uint(v1);
    hi = __byte_perm(u0, u1, 0x7632);
    float r0 = v0 - __uint_as_float(u0 & 0xffff0000u);
    float r1 = v1 - __uint_as_float(u1 & 0xffff0000u);
    asm("cvt.rn.bf16x2.f32 %0, %1, %2;" : "=r"(lo) : "f"(r1), "f"(r0));
}

// ---------------- tf32 GEMM: Y[M,N] = A[M,K] @ B[N,K]^T ----------------
// fp32 operands direct from gmem, in-register cvt.rna -> tf32.
// CTA 128x128, BK=32, 256 threads (8 warps 2x4, warp tile 64x32), 4-stage cp.async.
#define TROWF 36                          // 32 floats + 4 pad
#define TROWB (TROWF * 4)                 // 144 bytes
#define TMATB (128 * TROWB)               // 18432
#define TSTG  (2 * TMATB)                 // 36864 (A tile | B tile)
#define TNST  4
#define GEMM_SMEM (TNST * TSTG)           // 147456

__global__ __launch_bounds__(256, 1)
void gemm_tf32(const float* __restrict__ A0, const float* __restrict__ A1,
               const float* __restrict__ A2,
               const float* __restrict__ B0, const float* __restrict__ B1,
               const float* __restrict__ B2,
               float* __restrict__ Y,
               __nv_bfloat16* __restrict__ Yhi, __nv_bfloat16* __restrict__ Ylo,
               int split)
{
    extern __shared__ __align__(128) char smem[];
    const int K = 1024, N = 1024;
    const int tid = threadIdx.x;
    const int w = tid >> 5, lid = tid & 31;
    const int wm = w >> 2, wn = w & 3;
    const int gid = lid >> 2, t4 = lid & 3;
    const int z = blockIdx.z;
    const int brow = blockIdx.y * 128, bcol = blockIdx.x * 128;
    const uint32_t sb = smem_u32(smem);

    const float* Ap = ((z == 0) ? A0 : (z == 1) ? A1 : A2) + (size_t)brow * K;
    const float* Bp = ((z == 0) ? B0 : (z == 1) ? B1 : B2) + (size_t)bcol * K;

    auto load_stage = [&](int s) {
        const uint32_t base = sb + (s & (TNST - 1)) * TSTG;
        const int k0 = s * 32;
#pragma unroll
        for (int t = 0; t < 8; t++) {
            int i = tid + t * 256;
            int m = i >> 10, rem = i & 1023, r = rem >> 3, c = rem & 7;
            cp16(base + m * TMATB + r * TROWB + c * 16,
                 (m ? Bp : Ap) + (size_t)r * K + k0 + c * 4);
        }
        asm volatile("cp.async.commit_group;" ::: "memory");
    };

    float acc[4][4][4];
#pragma unroll
    for (int mt = 0; mt < 4; mt++)
#pragma unroll
        for (int nt = 0; nt < 4; nt++)
#pragma unroll
            for (int r = 0; r < 4; r++) acc[mt][nt][r] = 0.0f;

    load_stage(0);
    load_stage(1);
    load_stage(2);

#pragma unroll 1
    for (int s = 0; s < 32; s++) {
        asm volatile("cp.async.wait_group 2;" ::: "memory");
        __syncthreads();

        const float* As = (const float*)(smem + (s & (TNST - 1)) * TSTG);
        const float* Bs = (const float*)(smem + (s & (TNST - 1)) * TSTG + TMATB);

#pragma unroll
        for (int ks = 0; ks < 4; ks++) {
            const int kc = ks * 8 + t4;
            uint32_t af[4][4], bfr[4][2];
#pragma unroll
            for (int mt = 0; mt < 4; mt++) {
                int r0 = wm * 64 + mt * 16 + gid;
                af[mt][0] = tf32r(As[r0 * TROWF + kc]);
                af[mt][1] = tf32r(As[(r0 + 8) * TROWF + kc]);
                af[mt][2] = tf32r(As[r0 * TROWF + kc + 4]);
                af[mt][3] = tf32r(As[(r0 + 8) * TROWF + kc + 4]);
            }
#pragma unroll
            for (int nt = 0; nt < 4; nt++) {
                int n0 = wn * 32 + nt * 8 + gid;
                bfr[nt][0] = tf32r(Bs[n0 * TROWF + kc]);
                bfr[nt][1] = tf32r(Bs[n0 * TROWF + kc + 4]);
            }
#pragma unroll
            for (int mt = 0; mt < 4; mt++)
#pragma unroll
                for (int nt = 0; nt < 4; nt++)
                    mma1688t(acc[mt][nt], af[mt], bfr[nt][0], bfr[nt][1]);
        }

        if (s + 3 < 32) load_stage(s + 3);
        else asm volatile("cp.async.commit_group;" ::: "memory");
    }

    const size_t za = (size_t)z * ADM;
#pragma unroll
    for (int mt = 0; mt < 4; mt++) {
        int row0 = brow + wm * 64 + mt * 16 + gid;
#pragma unroll
        for (int nt = 0; nt < 4; nt++) {
            int col = bcol + wn * 32 + nt * 8 + t4 * 2;
            if (split) {
                uint32_t hh, ll;
                pack_hl(acc[mt][nt][0], acc[mt][nt][1], hh, ll);
                *(uint32_t*)&Yhi[za + (size_t)row0 * N + col] = hh;
                *(uint32_t*)&Ylo[za + (size_t)row0 * N + col] = ll;
                pack_hl(acc[mt][nt][2], acc[mt][nt][3], hh, ll);
                *(uint32_t*)&Yhi[za + (size_t)(row0 + 8) * N + col] = hh;
                *(uint32_t*)&Ylo[za + (size_t)(row0 + 8) * N + col] = ll;
            } else {
                *(float2*)(Y + (size_t)row0 * N + col) =
                    make_float2(acc[mt][nt][0], acc[mt][nt][1]);
                *(float2*)(Y + (size_t)(row0 + 8) * N + col) =
                    make_float2(acc[mt][nt][2], acc[mt][nt][3]);
            }
        }
    }
}

// ---------------- tensor-core causal flash attention (bf16x3) ----------------
#define AROWB  144
#define AMAT   (64 * AROWB)
#define ASTAGE (4 * AMAT)
#define AQ     (2 * 128 * AROWB)
#define FA_SMEM (AQ + 2 * ASTAGE)

__global__ __launch_bounds__(256, 1)
void flash_attn_mma(
    const __nv_bfloat16* __restrict__ Qhi, const __nv_bfloat16* __restrict__ Qlo,
    const __nv_bfloat16* __restrict__ Khi, const __nv_bfloat16* __restrict__ Klo,
    const __nv_bfloat16* __restrict__ Vhi, const __nv_bfloat16* __restrict__ Vlo,
    float* __restrict__ C)
{
    extern __shared__ __align__(128) char smem[];
    const int tid = threadIdx.x, w = tid >> 5, lid = tid & 31;
    const int gid = lid >> 2, t4 = lid & 3;
    const int qi = (SEQ / 128 - 1) - blockIdx.x;
    const int h = blockIdx.y, b = blockIdx.z;
    const int q0 = qi * 128;
    const int nt = 2 * qi + 2;
    const uint32_t sb = smem_u32(smem);
    const size_t gb = (size_t)b * SEQ * DM + (size_t)h * DK;

#pragma unroll
    for (int t = 0; t < 8; t++) {
        int i = tid + t * 256;
        int mt = i >> 10, rem = i & 1023, r = rem >> 3, c = rem & 7;
        const __nv_bfloat16* s = (mt ? Qlo : Qhi) + gb + (size_t)(q0 + r) * DM + c * 8;
        cp16(sb + mt * (128 * AROWB) + r * AROWB + c * 16, s);
    }
    asm volatile("cp.async.commit_group;" ::: "memory");

    auto load_kv = [&](int jt, int buf) {
        const uint32_t st = sb + AQ + buf * ASTAGE;
        const int k0 = jt * 64;
#pragma unroll
        for (int t = 0; t < 8; t++) {
            int i = tid + t * 256;
            int mt = i >> 9, rem = i & 511, r = rem >> 3, c = rem & 7;
            const __nv_bfloat16* s;
            if (mt == 0) s = Khi; else if (mt == 1) s = Klo;
            else if (mt == 2) s = Vhi; else s = Vlo;
            cp16(st + mt * AMAT + r * AROWB + c * 16,
                 s + gb + (size_t)(k0 + r) * DM + c * 8);
        }
        asm volatile("cp.async.commit_group;" ::: "memory");
    };

    load_kv(0, 0);

    float Oa[8][4];
    float m0 = -1e30f, m1 = -1e30f, l0 = 0.f, l1 = 0.f;
#pragma unroll
    for (int nf = 0; nf < 8; nf++)
#pragma unroll
        for (int c = 0; c < 4; c++) Oa[nf][c] = 0.f;

    const float SC = 0.18033688011112042f;   // 0.125 * log2(e)
    const uint32_t qaddr = sb + (w * 16 + (lid & 15)) * AROWB + ((lid >> 4) << 4);
    const uint32_t lrowoff = (((lid >> 3) & 1) * 8 + (lid & 7)) * AROWB + ((lid >> 4) << 4);

    for (int jt = 0; jt < nt; jt++) {
        if (jt + 1 < nt) {
            load_kv(jt + 1, (jt + 1) & 1);
            asm volatile("cp.async.wait_group 1;" ::: "memory");
        } else {
            asm volatile("cp.async.wait_group 0;" ::: "memory");
        }
        __syncthreads();

        const uint32_t st = sb + AQ + (jt & 1) * ASTAGE;
        const int k0 = jt * 64;

        uint32_t qh[4][4], ql[4][4];
#pragma unroll
        for (int ks = 0; ks < 4; ks++) {
            ldsm4(qh[ks][0], qh[ks][1], qh[ks][2], qh[ks][3], qaddr + ks * 32);
            ldsm4(ql[ks][0], ql[ks][1], ql[ks][2], ql[ks][3],
                  qaddr + 128 * AROWB + ks * 32);
        }

        float S[8][4];
#pragma unroll
        for (int nf = 0; nf < 8; nf++)
#pragma unroll
            for (int c = 0; c < 4; c++) S[nf][c] = 0.f;

#pragma unroll
        for (int g = 0; g < 4; g++) {
            uint32_t kh[4][4], kl[4][4];
#pragma unroll
            for (int ks = 0; ks < 4; ks++) {
                uint32_t ka = st + g * (16 * AROWB) + lrowoff + ks * 32;
                ldsm4(kh[ks][0], kh[ks][1], kh[ks][2], kh[ks][3], ka);
                ldsm4(kl[ks][0], kl[ks][1], kl[ks][2], kl[ks][3], ka + AMAT);
            }
#pragma unroll
            for (int ks = 0; ks < 4; ks++)
#pragma unroll
                for (int o = 0; o < 2; o++) {
                    mma16816(S[2 * g + o], qh[ks], kh[ks][o], kh[ks][o + 2]);
                    mma16816(S[2 * g + o], qh[ks], kl[ks][o], kl[ks][o + 2]);
                    mma16816(S[2 * g + o], ql[ks], kh[ks][o], kh[ks][o + 2]);
                }
        }

        const bool diag = (jt >= nt - 2);
        const int row0 = q0 + w * 16 + gid;
#pragma unroll
        for (int nf = 0; nf < 8; nf++) {
            int coln = k0 + nf * 8 + 2 * t4;
            S[nf][0] *= SC; S[nf][1] *= SC; S[nf][2] *= SC; S[nf][3] *= SC;
            if (diag) {
                if (coln     > row0)     S[nf][0] = -1e30f;
                if (coln + 1 > row0)     S[nf][1] = -1e30f;
                if (coln     > row0 + 8) S[nf][2] = -1e30f;
                if (coln + 1 > row0 + 8) S[nf][3] = -1e30f;
            }
        }
        float mx0 = -1e30f, mx1 = -1e30f;
#pragma unroll
        for (int nf = 0; nf < 8; nf++) {
            mx0 = fmaxf(mx0, fmaxf(S[nf][0], S[nf][1]));
            mx1 = fmaxf(mx1, fmaxf(S[nf][2], S[nf][3]));
        }
        mx0 = fmaxf(mx0, __shfl_xor_sync(0xffffffffu, mx0, 1));
        mx0 = fmaxf(mx0, __shfl_xor_sync(0xffffffffu, mx0, 2));
        mx1 = fmaxf(mx1, __shfl_xor_sync(0xffffffffu, mx1, 1));
        mx1 = fmaxf(mx1, __shfl_xor_sync(0xffffffffu, mx1, 2));

        float m0n = fmaxf(m0, mx0), m1n = fmaxf(m1, mx1);
        float a0 = ex2f(m0 - m0n), a1 = ex2f(m1 - m1n);
        m0 = m0n; m1 = m1n;

        float rs0 = 0.f, rs1 = 0.f;
        uint32_t phi[4][4], plo[4][4];
#pragma unroll
        for (int ks = 0; ks < 4; ks++)
#pragma unroll
            for (int half = 0; half < 2; half++) {
                int nf = 2 * ks + half;
                float p0 = ex2f(S[nf][0] - m0n);
                float p1 = ex2f(S[nf][1] - m0n);
                float p2 = ex2f(S[nf][2] - m1n);
                float p3 = ex2f(S[nf][3] - m1n);
                rs0 += p0 + p1; rs1 += p2 + p3;
                pack_hl(p0, p1, phi[ks][2 * half],     plo[ks][2 * half]);
                pack_hl(p2, p3, phi[ks][2 * half + 1], plo[ks][2 * half + 1]);
            }
        rs0 += __shfl_xor_sync(0xffffffffu, rs0, 1);
        rs0 += __shfl_xor_sync(0xffffffffu, rs0, 2);
        rs1 += __shfl_xor_sync(0xffffffffu, rs1, 1);
        rs1 += __shfl_xor_sync(0xffffffffu, rs1, 2);
        l0 = l0 * a0 + rs0;
        l1 = l1 * a1 + rs1;
#pragma unroll
        for (int nf = 0; nf < 8; nf++) {
            Oa[nf][0] *= a0; Oa[nf][1] *= a0;
            Oa[nf][2] *= a1; Oa[nf][3] *= a1;
        }

#pragma unroll
        for (int g = 0; g < 4; g++) {
            uint32_t vh[4][4], vl[4][4];
#pragma unroll
            for (int ks = 0; ks < 4; ks++) {
                uint32_t va = st + 2 * AMAT + ks * (16 * AROWB) + lrowoff + g * 32;
                ldsm4t(vh[ks][0], vh[ks][1], vh[ks][2], vh[ks][3], va);
                ldsm4t(vl[ks][0], vl[ks][1], vl[ks][2], vl[ks][3], va + AMAT);
            }
#pragma unroll
            for (int ks = 0; ks < 4; ks++)
#pragma unroll
                for (int o = 0; o < 2; o++) {
                    mma16816(Oa[2 * g + o], phi[ks], vh[ks][2 * o], vh[ks][2 * o + 1]);
                    mma16816(Oa[2 * g + o], phi[ks], vl[ks][2 * o], vl[ks][2 * o + 1]);
                    mma16816(Oa[2 * g + o], plo[ks], vh[ks][2 * o], vh[ks][2 * o + 1]);
                }
        }
        __syncthreads();
    }

    float il0 = 1.f / l0, il1 = 1.f / l1;
    const int row0 = q0 + w * 16 + gid;
#pragma unroll
    for (int nf = 0; nf < 8; nf++) {
        int col = nf * 8 + 2 * t4;
        size_t ad0 = gb + (size_t)row0 * DM + col;
        size_t ad1 = gb + (size_t)(row0 + 8) * DM + col;
        *(float2*)(C + ad0) = make_float2(Oa[nf][0] * il0, Oa[nf][1] * il0);
        *(float2*)(C + ad1) = make_float2(Oa[nf][2] * il1, Oa[nf][3] * il1);
    }
}

// ---------------- launch ----------------
extern "C" void kernel_launch(void* const* d_in, const int* in_sizes, int n_in,
                              void* d_out, int out_size)
{
    const float* q  = (const float*)d_in[0];
    const float* k  = (const float*)d_in[1];
    const float* v  = (const float*)d_in[2];
    const float* Wq = (const float*)d_in[4];
    const float* Wk = (const float*)d_in[5];
    const float* Wv = (const float*)d_in[6];
    const float* Wo = (const float*)d_in[7];
    float* out = (float*)d_out;

    __nv_bfloat16 *pjhi, *pjlo;
    float* ctx;
    cudaGetSymbolAddress((void**)&pjhi, g_pjhi);
    cudaGetSymbolAddress((void**)&pjlo, g_pjlo);
    cudaGetSymbolAddress((void**)&ctx,  g_ctx);

    cudaFuncSetAttribute(gemm_tf32, cudaFuncAttributeMaxDynamicSharedMemorySize,
                         GEMM_SMEM);
    cudaFuncSetAttribute(flash_attn_mma, cudaFuncAttributeMaxDynamicSharedMemorySize,
                         FA_SMEM);

    // Q/K/V projections (fp32 inputs direct, tf32 mma) -> bf16 hi/lo for attention
    gemm_tf32<<<dim3(DM / 128, MTOT / 128, 3), 256, GEMM_SMEM>>>(
        q, k, v, Wq, Wk, Wv, nullptr, pjhi, pjlo, 1);

    // attention (bf16x3) -> fp32 ctx
    flash_attn_mma<<<dim3(SEQ / 128, NHEAD, BATCH), 256, FA_SMEM>>>(
        pjhi, pjlo, pjhi + ADM, pjlo + ADM, pjhi + 2 * ADM, pjlo + 2 * ADM, ctx);

    // output projection (fp32 ctx + Wo direct, tf32 mma) -> fp32 out
    gemm_tf32<<<dim3(DM / 128, MTOT / 128, 1), 256, GEMM_SMEM>>>(
        ctx, nullptr, nullptr, Wo, nullptr, nullptr, out, nullptr, nullptr, 0);
}

// round 7
// speedup vs baseline: 3.9823x; 1.1330x over previous
#include <cuda_runtime.h>
#include <cuda_bf16.h>
#include <cstdint>

#define BATCH 4
#define SEQ   2048
#define DM    1024
#define NHEAD 16
#define DK    64
#define MTOT  (BATCH * SEQ)   // 8192
#define ADM   ((size_t)MTOT * DM)

// ---------------- scratch (no allocations allowed) ----------------
__device__ __align__(16) float g_proj[3 * ADM];   // Q|K|V (tf32-prerounded fp32)
__device__ __align__(16) float g_ctx [ADM];       // attention output

// ---------------- PTX helpers (base sm_103 ISA only) ----------------
__device__ __forceinline__ uint32_t smem_u32(const void* p) {
    uint32_t a;
    asm("{ .reg .u64 t; cvta.to.shared.u64 t, %1; cvt.u32.u64 %0, t; }"
        : "=r"(a) : "l"(p));
    return a;
}

__device__ __forceinline__ void cp16(uint32_t dst, const void* src) {
    asm volatile("cp.async.cg.shared.global [%0], [%1], 16;"
                 :: "r"(dst), "l"(src));
}

__device__ __forceinline__ void mma1688t(float* c, const uint32_t* a,
                                         uint32_t b0, uint32_t b1) {
    asm volatile(
        "mma.sync.aligned.m16n8k8.row.col.f32.tf32.tf32.f32 "
        "{%0,%1,%2,%3}, {%4,%5,%6,%7}, {%8,%9}, {%0,%1,%2,%3};"
        : "+f"(c[0]), "+f"(c[1]), "+f"(c[2]), "+f"(c[3])
        : "r"(a[0]), "r"(a[1]), "r"(a[2]), "r"(a[3]), "r"(b0), "r"(b1));
}

__device__ __forceinline__ uint32_t tf32r(float x) {
    uint32_t y;
    asm("cvt.rna.tf32.f32 %0, %1;" : "=r"(y) : "f"(x));
    return y;
}

__device__ __forceinline__ float ex2f(float x) {
    float y;
    asm("ex2.approx.f32 %0, %1;" : "=f"(y) : "f"(x));
    return y;
}

// ---------------- tf32 GEMM: Y[M,N] = A[M,K] @ B[N,K]^T ----------------
// CTA 128x128, BK=32, 256 threads (8 warps 2x4), 3-stage cp.async, 2 CTAs/SM.
#define TROWF 36                          // 32 floats + 4 pad
#define TROWB (TROWF * 4)                 // 144 bytes
#define TMATB (128 * TROWB)               // 18432
#define TSTG  (2 * TMATB)                 // 36864 (A | B)
#define TNST  3
#define GEMM_SMEM (TNST * TSTG)           // 110592

__global__ __launch_bounds__(256, 2)
void gemm_tf32(const float* __restrict__ A0, const float* __restrict__ A1,
               const float* __restrict__ A2,
               const float* __restrict__ B0, const float* __restrict__ B1,
               const float* __restrict__ B2,
               float* __restrict__ Y, int round_out)
{
    extern __shared__ __align__(128) char smem[];
    const int K = 1024, N = 1024;
    const int tid = threadIdx.x;
    const int w = tid >> 5, lid = tid & 31;
    const int wm = w >> 2, wn = w & 3;
    const int gid = lid >> 2, t4 = lid & 3;
    const int z = blockIdx.z;
    const int brow = blockIdx.y * 128, bcol = blockIdx.x * 128;
    const uint32_t sb = smem_u32(smem);

    const float* Ap = ((z == 0) ? A0 : (z == 1) ? A1 : A2) + (size_t)brow * K;
    const float* Bp = ((z == 0) ? B0 : (z == 1) ? B1 : B2) + (size_t)bcol * K;

    auto load_stage = [&](int s) {
        const uint32_t base = sb + (s % TNST) * TSTG;
        const int k0 = s * 32;
#pragma unroll
        for (int t = 0; t < 8; t++) {
            int i = tid + t * 256;
            int m = i >> 10, rem = i & 1023, r = rem >> 3, c = rem & 7;
            cp16(base + m * TMATB + r * TROWB + c * 16,
                 (m ? Bp : Ap) + (size_t)r * K + k0 + c * 4);
        }
        asm volatile("cp.async.commit_group;" ::: "memory");
    };

    float acc[4][4][4];
#pragma unroll
    for (int mt = 0; mt < 4; mt++)
#pragma unroll
        for (int nt = 0; nt < 4; nt++)
#pragma unroll
            for (int r = 0; r < 4; r++) acc[mt][nt][r] = 0.0f;

    load_stage(0);
    load_stage(1);
    load_stage(2);

#pragma unroll 1
    for (int s = 0; s < 32; s++) {
        asm volatile("cp.async.wait_group 2;" ::: "memory");
        __syncthreads();

        const float* As = (const float*)(smem + (s % TNST) * TSTG);
        const float* Bs = (const float*)(smem + (s % TNST) * TSTG + TMATB);

#pragma unroll
        for (int ks = 0; ks < 4; ks++) {
            const int kc = ks * 8 + t4;
            uint32_t af[4][4], bfr[4][2];
#pragma unroll
            for (int mt = 0; mt < 4; mt++) {
                int r0 = wm * 64 + mt * 16 + gid;
                af[mt][0] = tf32r(As[r0 * TROWF + kc]);
                af[mt][1] = tf32r(As[(r0 + 8) * TROWF + kc]);
                af[mt][2] = tf32r(As[r0 * TROWF + kc + 4]);
                af[mt][3] = tf32r(As[(r0 + 8) * TROWF + kc + 4]);
            }
#pragma unroll
            for (int nt = 0; nt < 4; nt++) {
                int n0 = wn * 32 + nt * 8 + gid;
                bfr[nt][0] = tf32r(Bs[n0 * TROWF + kc]);
                bfr[nt][1] = tf32r(Bs[n0 * TROWF + kc + 4]);
            }
#pragma unroll
            for (int mt = 0; mt < 4; mt++)
#pragma unroll
                for (int nt = 0; nt < 4; nt++)
                    mma1688t(acc[mt][nt], af[mt], bfr[nt][0], bfr[nt][1]);
        }

        __syncthreads();
        if (s + 3 < 32) load_stage(s + 3);
        else asm volatile("cp.async.commit_group;" ::: "memory");
    }

    float* Yp = Y + (size_t)z * ADM * (round_out ? 1 : 0);  // z==0 when !round_out
#pragma unroll
    for (int mt = 0; mt < 4; mt++) {
        int row0 = brow + wm * 64 + mt * 16 + gid;
#pragma unroll
        for (int nt = 0; nt < 4; nt++) {
            int col = bcol + wn * 32 + nt * 8 + t4 * 2;
            float o0 = acc[mt][nt][0], o1 = acc[mt][nt][1];
            float o2 = acc[mt][nt][2], o3 = acc[mt][nt][3];
            if (round_out) {
                o0 = __uint_as_float(tf32r(o0)); o1 = __uint_as_float(tf32r(o1));
                o2 = __uint_as_float(tf32r(o2)); o3 = __uint_as_float(tf32r(o3));
            }
            *(float2*)(Yp + (size_t)row0 * N + col) = make_float2(o0, o1);
            *(float2*)(Yp + (size_t)(row0 + 8) * N + col) = make_float2(o2, o3);
        }
    }
}

// ---------------- full-tf32 causal flash attention ----------------
// CTA: 128 q-rows x (b,h); 8 warps x 16 rows; kv tiles of 64.
// Q/P share one smem region (stride 68 floats); K stride 68; V stride 72.
#define QROW 68
#define VROW 72
#define QPB  (128 * QROW * 4)             // 34816
#define KB   (64 * QROW * 4)              // 17408
#define VB   (64 * VROW * 4)              // 18432
#define KVSTG (KB + VB)                   // 35840
#define FA_SMEM (QPB + 2 * KVSTG)         // 106496

__global__ __launch_bounds__(256, 1)
void flash_attn_tf32(const float* __restrict__ Q, const float* __restrict__ K,
                     const float* __restrict__ V, float* __restrict__ C)
{
    extern __shared__ __align__(128) char smem[];
    float* fsm = (float*)smem;
    const int tid = threadIdx.x, w = tid >> 5, lid = tid & 31;
    const int gid = lid >> 2, t4 = lid & 3;
    const int qi = (SEQ / 128 - 1) - blockIdx.x;   // big tiles first
    const int h = blockIdx.y, b = blockIdx.z;
    const int q0 = qi * 128;
    const int nt = 2 * qi + 2;
    const uint32_t sb = smem_u32(smem);
    const size_t gb = (size_t)b * SEQ * DM + (size_t)h * DK;

    // Q tile -> smem (group 0): 128 rows x 64 floats
#pragma unroll
    for (int t = 0; t < 8; t++) {
        int i = tid + t * 256;
        int r = i >> 4, c = i & 15;
        cp16(sb + r * (QROW * 4) + c * 16, Q + gb + (size_t)(q0 + r) * DM + c * 4);
    }
    asm volatile("cp.async.commit_group;" ::: "memory");

    auto load_kv = [&](int jt, int buf) {
        const uint32_t kst = sb + QPB + buf * KVSTG;
        const uint32_t vst = kst + KB;
        const int k0 = jt * 64;
#pragma unroll
        for (int t = 0; t < 8; t++) {
            int i = tid + t * 256;
            int m = i >> 10, rem = i & 1023, r = rem >> 4, c = rem & 15;
            if (m == 0)
                cp16(kst + r * (QROW * 4) + c * 16,
                     K + gb + (size_t)(k0 + r) * DM + c * 4);
            else
                cp16(vst + r * (VROW * 4) + c * 16,
                     V + gb + (size_t)(k0 + r) * DM + c * 4);
        }
        asm volatile("cp.async.commit_group;" ::: "memory");
    };

    load_kv(0, 0);

    uint32_t qa[8][4];
    float Oa[8][4];
    float m0 = -1e30f, m1 = -1e30f, l0 = 0.f, l1 = 0.f;
#pragma unroll
    for (int nf = 0; nf < 8; nf++)
#pragma unroll
        for (int c = 0; c < 4; c++) Oa[nf][c] = 0.f;

    const float SC = 0.18033688011112042f;   // 0.125 * log2(e)
    const int qrow = w * 16 + gid;           // this thread's base q-row (local)

    for (int jt = 0; jt < nt; jt++) {
        if (jt + 1 < nt) {
            load_kv(jt + 1, (jt + 1) & 1);
            asm volatile("cp.async.wait_group 1;" ::: "memory");
        } else {
            asm volatile("cp.async.wait_group 0;" ::: "memory");
        }
        __syncthreads();

        const float* Ks = fsm + (QPB + (jt & 1) * KVSTG) / 4;
        const float* Vs = Ks + KB / 4;
        const int k0 = jt * 64;

        if (jt == 0) {
            // extract Q frags (Q prerounded tf32 -> raw bits valid)
            const uint32_t* Qs = (const uint32_t*)fsm;
#pragma unroll
            for (int j = 0; j < 8; j++) {
                qa[j][0] = Qs[qrow * QROW + 8 * j + t4];
                qa[j][1] = Qs[(qrow + 8) * QROW + 8 * j + t4];
                qa[j][2] = Qs[qrow * QROW + 8 * j + t4 + 4];
                qa[j][3] = Qs[(qrow + 8) * QROW + 8 * j + t4 + 4];
            }
        }

        // ---- S = Q K^T (tf32)
        float S[8][4];
#pragma unroll
        for (int nf = 0; nf < 8; nf++)
#pragma unroll
            for (int c = 0; c < 4; c++) S[nf][c] = 0.f;

        const uint32_t* Ku = (const uint32_t*)Ks;
#pragma unroll
        for (int j = 0; j < 8; j++) {
#pragma unroll
            for (int nf = 0; nf < 8; nf++) {
                uint32_t b0 = Ku[(8 * nf + gid) * QROW + 8 * j + t4];
                uint32_t b1 = Ku[(8 * nf + gid) * QROW + 8 * j + t4 + 4];
                mma1688t(S[nf], qa[j], b0, b1);
            }
        }

        // ---- softmax (base-2 domain)
        const bool diag = (jt >= nt - 2);
        const int row0 = q0 + qrow;
#pragma unroll
        for (int nf = 0; nf < 8; nf++) {
            int coln = k0 + nf * 8 + 2 * t4;
            S[nf][0] *= SC; S[nf][1] *= SC; S[nf][2] *= SC; S[nf][3] *= SC;
            if (diag) {
                if (coln     > row0)     S[nf][0] = -1e30f;
                if (coln + 1 > row0)     S[nf][1] = -1e30f;
                if (coln     > row0 + 8) S[nf][2] = -1e30f;
                if (coln + 1 > row0 + 8) S[nf][3] = -1e30f;
            }
        }
        float mx0 = -1e30f, mx1 = -1e30f;
#pragma unroll
        for (int nf = 0; nf < 8; nf++) {
            mx0 = fmaxf(mx0, fmaxf(S[nf][0], S[nf][1]));
            mx1 = fmaxf(mx1, fmaxf(S[nf][2], S[nf][3]));
        }
        mx0 = fmaxf(mx0, __shfl_xor_sync(0xffffffffu, mx0, 1));
        mx0 = fmaxf(mx0, __shfl_xor_sync(0xffffffffu, mx0, 2));
        mx1 = fmaxf(mx1, __shfl_xor_sync(0xffffffffu, mx1, 1));
        mx1 = fmaxf(mx1, __shfl_xor_sync(0xffffffffu, mx1, 2));

        float m0n = fmaxf(m0, mx0), m1n = fmaxf(m1, mx1);
        float a0 = ex2f(m0 - m0n), a1 = ex2f(m1 - m1n);
        m0 = m0n; m1 = m1n;

        // P = exp2(S - m); round to tf32; stash in Q/P smem region (own rows only)
        float rs0 = 0.f, rs1 = 0.f;
        float* Ps = fsm;
#pragma unroll
        for (int nf = 0; nf < 8; nf++) {
            float p0 = ex2f(S[nf][0] - m0n);
            float p1 = ex2f(S[nf][1] - m0n);
            float p2 = ex2f(S[nf][2] - m1n);
            float p3 = ex2f(S[nf][3] - m1n);
            rs0 += p0 + p1; rs1 += p2 + p3;
            int colp = nf * 8 + 2 * t4;
            *(float2*)(Ps + qrow * QROW + colp) =
                make_float2(__uint_as_float(tf32r(p0)), __uint_as_float(tf32r(p1)));
            *(float2*)(Ps + (qrow + 8) * QROW + colp) =
                make_float2(__uint_as_float(tf32r(p2)), __uint_as_float(tf32r(p3)));
        }
        rs0 += __shfl_xor_sync(0xffffffffu, rs0, 1);
        rs0 += __shfl_xor_sync(0xffffffffu, rs0, 2);
        rs1 += __shfl_xor_sync(0xffffffffu, rs1, 1);
        rs1 += __shfl_xor_sync(0xffffffffu, rs1, 2);
        l0 = l0 * a0 + rs0;
        l1 = l1 * a1 + rs1;
#pragma unroll
        for (int nf = 0; nf < 8; nf++) {
            Oa[nf][0] *= a0; Oa[nf][1] *= a0;
            Oa[nf][2] *= a1; Oa[nf][3] *= a1;
        }
        __syncwarp();

        // ---- O += P V (tf32); P from smem (A frags), V from smem (B frags)
        const uint32_t* Pu = (const uint32_t*)fsm;
        const uint32_t* Vu = (const uint32_t*)Vs;
#pragma unroll
        for (int j = 0; j < 8; j++) {
            uint32_t pa[4];
            pa[0] = Pu[qrow * QROW + 8 * j + t4];
            pa[1] = Pu[(qrow + 8) * QROW + 8 * j + t4];
            pa[2] = Pu[qrow * QROW + 8 * j + t4 + 4];
            pa[3] = Pu[(qrow + 8) * QROW + 8 * j + t4 + 4];
#pragma unroll
            for (int nf = 0; nf < 8; nf++) {
                uint32_t b0 = Vu[(8 * j + t4) * VROW + 8 * nf + gid];
                uint32_t b1 = Vu[(8 * j + t4 + 4) * VROW + 8 * nf + gid];
                mma1688t(Oa[nf], pa, b0, b1);
            }
        }
        __syncthreads();
    }

    // ---- epilogue: ctx = O / l (fp32)
    float il0 = 1.f / l0, il1 = 1.f / l1;
    const int row0 = q0 + qrow;
#pragma unroll
    for (int nf = 0; nf < 8; nf++) {
        int col = nf * 8 + 2 * t4;
        size_t ad0 = gb + (size_t)row0 * DM + col;
        size_t ad1 = gb + (size_t)(row0 + 8) * DM + col;
        *(float2*)(C + ad0) = make_float2(Oa[nf][0] * il0, Oa[nf][1] * il0);
        *(float2*)(C + ad1) = make_float2(Oa[nf][2] * il1, Oa[nf][3] * il1);
    }
}

// ---------------- launch ----------------
extern "C" void kernel_launch(void* const* d_in, const int* in_sizes, int n_in,
                              void* d_out, int out_size)
{
    const float* q  = (const float*)d_in[0];
    const float* k  = (const float*)d_in[1];
    const float* v  = (const float*)d_in[2];
    const float* Wq = (const float*)d_in[4];
    const float* Wk = (const float*)d_in[5];
    const float* Wv = (const float*)d_in[6];
    const float* Wo = (const float*)d_in[7];
    float* out = (float*)d_out;

    float *proj, *ctx;
    cudaGetSymbolAddress((void**)&proj, g_proj);
    cudaGetSymbolAddress((void**)&ctx,  g_ctx);

    cudaFuncSetAttribute(gemm_tf32, cudaFuncAttributeMaxDynamicSharedMemorySize,
                         GEMM_SMEM);
    cudaFuncSetAttribute(flash_attn_tf32,
                         cudaFuncAttributeMaxDynamicSharedMemorySize, FA_SMEM);

    // Q/K/V projections -> tf32-prerounded fp32
    gemm_tf32<<<dim3(DM / 128, MTOT / 128, 3), 256, GEMM_SMEM>>>(
        q, k, v, Wq, Wk, Wv, proj, 1);

    // full-tf32 attention -> fp32 ctx
    flash_attn_tf32<<<dim3(SEQ / 128, NHEAD, BATCH), 256, FA_SMEM>>>(
        proj, proj + ADM, proj + 2 * ADM, ctx);

    // output projection -> fp32 out
    gemm_tf32<<<dim3(DM / 128, MTOT / 128, 1), 256, GEMM_SMEM>>>(
        ctx, nullptr, nullptr, Wo, nullptr, nullptr, out, 0);
}

// round 8
// speedup vs baseline: 3.9974x; 1.0038x over previous
#include <cuda_runtime.h>
#include <cuda_bf16.h>
#include <cstdint>

#define BATCH 4
#define SEQ   2048
#define DM    1024
#define NHEAD 16
#define DK    64
#define MTOT  (BATCH * SEQ)   // 8192
#define ADM   ((size_t)MTOT * DM)

// ---------------- scratch (no allocations allowed) ----------------
__device__ __align__(16) float g_proj[3 * ADM];   // Q|K|V (tf32-prerounded fp32)
__device__ __align__(16) float g_ctx [ADM];       // attention output

// ---------------- PTX helpers (base sm_103 ISA only) ----------------
__device__ __forceinline__ uint32_t smem_u32(const void* p) {
    uint32_t a;
    asm("{ .reg .u64 t; cvta.to.shared.u64 t, %1; cvt.u32.u64 %0, t; }"
        : "=r"(a) : "l"(p));
    return a;
}

__device__ __forceinline__ void cp16(uint32_t dst, const void* src) {
    asm volatile("cp.async.cg.shared.global [%0], [%1], 16;"
                 :: "r"(dst), "l"(src));
}

__device__ __forceinline__ void mma1688t(float* c, const uint32_t* a,
                                         uint32_t b0, uint32_t b1) {
    asm volatile(
        "mma.sync.aligned.m16n8k8.row.col.f32.tf32.tf32.f32 "
        "{%0,%1,%2,%3}, {%4,%5,%6,%7}, {%8,%9}, {%0,%1,%2,%3};"
        : "+f"(c[0]), "+f"(c[1]), "+f"(c[2]), "+f"(c[3])
        : "r"(a[0]), "r"(a[1]), "r"(a[2]), "r"(a[3]), "r"(b0), "r"(b1));
}

__device__ __forceinline__ uint32_t tf32r(float x) {
    uint32_t y;
    asm("cvt.rna.tf32.f32 %0, %1;" : "=r"(y) : "f"(x));
    return y;
}

__device__ __forceinline__ float ex2f(float x) {
    float y;
    asm("ex2.approx.f32 %0, %1;" : "=f"(y) : "f"(x));
    return y;
}

// ---------------- tf32 GEMM: Y[M,N] = A[M,K] @ B[N,K]^T ----------------
// CTA 128x128, BK=32, 256 threads (8 warps 2x4), 3-stage cp.async, 2 CTAs/SM.
#define TROWF 36
#define TROWB (TROWF * 4)                 // 144 bytes
#define TMATB (128 * TROWB)               // 18432
#define TSTG  (2 * TMATB)                 // 36864 (A | B)
#define TNST  3
#define GEMM_SMEM (TNST * TSTG)           // 110592

__global__ __launch_bounds__(256, 2)
void gemm_tf32(const float* __restrict__ A0, const float* __restrict__ A1,
               const float* __restrict__ A2,
               const float* __restrict__ B0, const float* __restrict__ B1,
               const float* __restrict__ B2,
               float* __restrict__ Y, int round_out)
{
    extern __shared__ __align__(128) char smem[];
    const int K = 1024, N = 1024;
    const int tid = threadIdx.x;
    const int w = tid >> 5, lid = tid & 31;
    const int wm = w >> 2, wn = w & 3;
    const int gid = lid >> 2, t4 = lid & 3;
    const int z = blockIdx.z;
    const int brow = blockIdx.y * 128, bcol = blockIdx.x * 128;
    const uint32_t sb = smem_u32(smem);

    const float* Ap = ((z == 0) ? A0 : (z == 1) ? A1 : A2) + (size_t)brow * K;
    const float* Bp = ((z == 0) ? B0 : (z == 1) ? B1 : B2) + (size_t)bcol * K;

    auto load_stage = [&](int s) {
        const uint32_t base = sb + (s % TNST) * TSTG;
        const int k0 = s * 32;
#pragma unroll
        for (int t = 0; t < 8; t++) {
            int i = tid + t * 256;
            int m = i >> 10, rem = i & 1023, r = rem >> 3, c = rem & 7;
            cp16(base + m * TMATB + r * TROWB + c * 16,
                 (m ? Bp : Ap) + (size_t)r * K + k0 + c * 4);
        }
        asm volatile("cp.async.commit_group;" ::: "memory");
    };

    float acc[4][4][4];
#pragma unroll
    for (int mt = 0; mt < 4; mt++)
#pragma unroll
        for (int nt = 0; nt < 4; nt++)
#pragma unroll
            for (int r = 0; r < 4; r++) acc[mt][nt][r] = 0.0f;

    load_stage(0);
    load_stage(1);
    load_stage(2);

#pragma unroll 1
    for (int s = 0; s < 32; s++) {
        asm volatile("cp.async.wait_group 2;" ::: "memory");
        __syncthreads();

        const float* As = (const float*)(smem + (s % TNST) * TSTG);
        const float* Bs = (const float*)(smem + (s % TNST) * TSTG + TMATB);

#pragma unroll
        for (int ks = 0; ks < 4; ks++) {
            const int kc = ks * 8 + t4;
            uint32_t af[4][4], bfr[4][2];
#pragma unroll
            for (int mt = 0; mt < 4; mt++) {
                int r0 = wm * 64 + mt * 16 + gid;
                af[mt][0] = tf32r(As[r0 * TROWF + kc]);
                af[mt][1] = tf32r(As[(r0 + 8) * TROWF + kc]);
                af[mt][2] = tf32r(As[r0 * TROWF + kc + 4]);
                af[mt][3] = tf32r(As[(r0 + 8) * TROWF + kc + 4]);
            }
#pragma unroll
            for (int nt = 0; nt < 4; nt++) {
                int n0 = wn * 32 + nt * 8 + gid;
                bfr[nt][0] = tf32r(Bs[n0 * TROWF + kc]);
                bfr[nt][1] = tf32r(Bs[n0 * TROWF + kc + 4]);
            }
#pragma unroll
            for (int mt = 0; mt < 4; mt++)
#pragma unroll
                for (int nt = 0; nt < 4; nt++)
                    mma1688t(acc[mt][nt], af[mt], bfr[nt][0], bfr[nt][1]);
        }

        __syncthreads();
        if (s + 3 < 32) load_stage(s + 3);
        else asm volatile("cp.async.commit_group;" ::: "memory");
    }

    float* Yp = Y + (size_t)z * ADM * (round_out ? 1 : 0);
#pragma unroll
    for (int mt = 0; mt < 4; mt++) {
        int row0 = brow + wm * 64 + mt * 16 + gid;
#pragma unroll
        for (int nt = 0; nt < 4; nt++) {
            int col = bcol + wn * 32 + nt * 8 + t4 * 2;
            float o0 = acc[mt][nt][0], o1 = acc[mt][nt][1];
            float o2 = acc[mt][nt][2], o3 = acc[mt][nt][3];
            if (round_out) {
                o0 = __uint_as_float(tf32r(o0)); o1 = __uint_as_float(tf32r(o1));
                o2 = __uint_as_float(tf32r(o2)); o3 = __uint_as_float(tf32r(o3));
            }
            *(float2*)(Yp + (size_t)row0 * N + col) = make_float2(o0, o1);
            *(float2*)(Yp + (size_t)(row0 + 8) * N + col) = make_float2(o2, o3);
        }
    }
}

// ---------------- full-tf32 causal flash attention (64-row CTA, occ 3) ----------------
// CTA: 64 q-rows x (b,h); 4 warps x 16 rows; kv tiles of 64, single-buffered.
#define QROW 68
#define VROW 72
#define QPB  (64 * QROW * 4)              // 17408  (Q, later P)
#define KOFF QPB                          // K at 17408
#define VOFF (KOFF + 64 * QROW * 4)       // V at 34816
#define FA_SMEM (VOFF + 64 * VROW * 4)    // 53248

__global__ __launch_bounds__(128, 3)
void flash_attn_tf32(const float* __restrict__ Q, const float* __restrict__ K,
                     const float* __restrict__ V, float* __restrict__ C)
{
    extern __shared__ __align__(128) char smem[];
    float* fsm = (float*)smem;
    const int tid = threadIdx.x, w = tid >> 5, lid = tid & 31;
    const int gid = lid >> 2, t4 = lid & 3;
    const int qi = (SEQ / 64 - 1) - blockIdx.x;   // big tiles first
    const int h = blockIdx.y, b = blockIdx.z;
    const int q0 = qi * 64;
    const int nt = qi + 1;
    const uint32_t sb = smem_u32(smem);
    const size_t gb = (size_t)b * SEQ * DM + (size_t)h * DK;

    // Q tile -> smem: 64 rows x 64 floats (waited together with first KV tile)
#pragma unroll
    for (int t = 0; t < 8; t++) {
        int i = tid + t * 128;
        int r = i >> 4, c = i & 15;
        cp16(sb + r * (QROW * 4) + c * 16, Q + gb + (size_t)(q0 + r) * DM + c * 4);
    }

    uint32_t qa[8][4];
    float Oa[8][4];
    float m0 = -1e30f, m1 = -1e30f, l0 = 0.f, l1 = 0.f;
#pragma unroll
    for (int nf = 0; nf < 8; nf++)
#pragma unroll
        for (int c = 0; c < 4; c++) Oa[nf][c] = 0.f;

    const float SC = 0.18033688011112042f;   // 0.125 * log2(e)
    const int qrow = w * 16 + gid;           // thread's base q-row (local)
    const int fmax = 2 * w + 2;              // frags this warp needs on diag tile

#pragma unroll 1
    for (int jt = 0; jt < nt; jt++) {
        if (jt > 0) __syncthreads();         // prior tile done reading K/V
        // load K/V tile jt (single buffer)
        {
            const int k0 = jt * 64;
#pragma unroll
            for (int t = 0; t < 16; t++) {
                int i = tid + t * 128;
                int m = i >> 10, rem = i & 1023, r = rem >> 4, c = rem & 15;
                if (m == 0)
                    cp16(sb + KOFF + r * (QROW * 4) + c * 16,
                         K + gb + (size_t)(k0 + r) * DM + c * 4);
                else
                    cp16(sb + VOFF + r * (VROW * 4) + c * 16,
                         V + gb + (size_t)(k0 + r) * DM + c * 4);
            }
            asm volatile("cp.async.commit_group;" ::: "memory");
            asm volatile("cp.async.wait_group 0;" ::: "memory");
        }
        __syncthreads();

        const int k0 = jt * 64;
        const bool diag = (jt == nt - 1);
        const int nfm = diag ? fmax : 8;

        if (jt == 0) {
            const uint32_t* Qs = (const uint32_t*)fsm;
#pragma unroll
            for (int j = 0; j < 8; j++) {
                qa[j][0] = Qs[qrow * QROW + 8 * j + t4];
                qa[j][1] = Qs[(qrow + 8) * QROW + 8 * j + t4];
                qa[j][2] = Qs[qrow * QROW + 8 * j + t4 + 4];
                qa[j][3] = Qs[(qrow + 8) * QROW + 8 * j + t4 + 4];
            }
        }

        // ---- S = Q K^T (tf32); skip fully-masked frags on diag tile
        float S[8][4];
#pragma unroll
        for (int nf = 0; nf < 8; nf++)
#pragma unroll
            for (int c = 0; c < 4; c++) S[nf][c] = 0.f;

        const uint32_t* Ku = (const uint32_t*)(fsm + KOFF / 4);
#pragma unroll
        for (int j = 0; j < 8; j++) {
#pragma unroll
            for (int nf = 0; nf < 8; nf++) {
                if (nf >= nfm) break;
                uint32_t b0 = Ku[(8 * nf + gid) * QROW + 8 * j + t4];
                uint32_t b1 = Ku[(8 * nf + gid) * QROW + 8 * j + t4 + 4];
                mma1688t(S[nf], qa[j], b0, b1);
            }
        }

        // ---- softmax (base-2 domain)
        const int row0 = q0 + qrow;
#pragma unroll
        for (int nf = 0; nf < 8; nf++) {
            int coln = k0 + nf * 8 + 2 * t4;
            S[nf][0] *= SC; S[nf][1] *= SC; S[nf][2] *= SC; S[nf][3] *= SC;
            if (diag) {
                if (coln     > row0)     S[nf][0] = -1e30f;
                if (coln + 1 > row0)     S[nf][1] = -1e30f;
                if (coln     > row0 + 8) S[nf][2] = -1e30f;
                if (coln + 1 > row0 + 8) S[nf][3] = -1e30f;
            }
        }
        float mx0 = -1e30f, mx1 = -1e30f;
#pragma unroll
        for (int nf = 0; nf < 8; nf++) {
            mx0 = fmaxf(mx0, fmaxf(S[nf][0], S[nf][1]));
            mx1 = fmaxf(mx1, fmaxf(S[nf][2], S[nf][3]));
        }
        mx0 = fmaxf(mx0, __shfl_xor_sync(0xffffffffu, mx0, 1));
        mx0 = fmaxf(mx0, __shfl_xor_sync(0xffffffffu, mx0, 2));
        mx1 = fmaxf(mx1, __shfl_xor_sync(0xffffffffu, mx1, 1));
        mx1 = fmaxf(mx1, __shfl_xor_sync(0xffffffffu, mx1, 2));

        float m0n = fmaxf(m0, mx0), m1n = fmaxf(m1, mx1);
        float a0 = ex2f(m0 - m0n), a1 = ex2f(m1 - m1n);
        m0 = m0n; m1 = m1n;

        // P = exp2(S - m), tf32-rounded, stashed over Q region (own rows only)
        float rs0 = 0.f, rs1 = 0.f;
        float* Ps = fsm;
#pragma unroll
        for (int nf = 0; nf < 8; nf++) {
            float p0 = ex2f(S[nf][0] - m0n);
            float p1 = ex2f(S[nf][1] - m0n);
            float p2 = ex2f(S[nf][2] - m1n);
            float p3 = ex2f(S[nf][3] - m1n);
            rs0 += p0 + p1; rs1 += p2 + p3;
            int colp = nf * 8 + 2 * t4;
            *(float2*)(Ps + qrow * QROW + colp) =
                make_float2(__uint_as_float(tf32r(p0)), __uint_as_float(tf32r(p1)));
            *(float2*)(Ps + (qrow + 8) * QROW + colp) =
                make_float2(__uint_as_float(tf32r(p2)), __uint_as_float(tf32r(p3)));
        }
        rs0 += __shfl_xor_sync(0xffffffffu, rs0, 1);
        rs0 += __shfl_xor_sync(0xffffffffu, rs0, 2);
        rs1 += __shfl_xor_sync(0xffffffffu, rs1, 1);
        rs1 += __shfl_xor_sync(0xffffffffu, rs1, 2);
        l0 = l0 * a0 + rs0;
        l1 = l1 * a1 + rs1;
#pragma unroll
        for (int nf = 0; nf < 8; nf++) {
            Oa[nf][0] *= a0; Oa[nf][1] *= a0;
            Oa[nf][2] *= a1; Oa[nf][3] *= a1;
        }
        __syncwarp();

        // ---- O += P V (tf32); skip all-zero kv-position groups on diag tile
        const uint32_t* Pu = (const uint32_t*)fsm;
        const uint32_t* Vu = (const uint32_t*)(fsm + VOFF / 4);
#pragma unroll
        for (int j = 0; j < 8; j++) {
            if (diag && j >= fmax) break;
            uint32_t pa[4];
            pa[0] = Pu[qrow * QROW + 8 * j + t4];
            pa[1] = Pu[(qrow + 8) * QROW + 8 * j + t4];
            pa[2] = Pu[qrow * QROW + 8 * j + t4 + 4];
            pa[3] = Pu[(qrow + 8) * QROW + 8 * j + t4 + 4];
#pragma unroll
            for (int nf = 0; nf < 8; nf++) {
                uint32_t b0 = Vu[(8 * j + t4) * VROW + 8 * nf + gid];
                uint32_t b1 = Vu[(8 * j + t4 + 4) * VROW + 8 * nf + gid];
                mma1688t(Oa[nf], pa, b0, b1);
            }
        }
    }

    // ---- epilogue: ctx = O / l (fp32)
    float il0 = 1.f / l0, il1 = 1.f / l1;
    const int row0 = q0 + qrow;
#pragma unroll
    for (int nf = 0; nf < 8; nf++) {
        int col = nf * 8 + 2 * t4;
        size_t ad0 = gb + (size_t)row0 * DM + col;
        size_t ad1 = gb + (size_t)(row0 + 8) * DM + col;
        *(float2*)(C + ad0) = make_float2(Oa[nf][0] * il0, Oa[nf][1] * il0);
        *(float2*)(C + ad1) = make_float2(Oa[nf][2] * il1, Oa[nf][3] * il1);
    }
}

// ---------------- launch ----------------
extern "C" void kernel_launch(void* const* d_in, const int* in_sizes, int n_in,
                              void* d_out, int out_size)
{
    const float* q  = (const float*)d_in[0];
    const float* k  = (const float*)d_in[1];
    const float* v  = (const float*)d_in[2];
    const float* Wq = (const float*)d_in[4];
    const float* Wk = (const float*)d_in[5];
    const float* Wv = (const float*)d_in[6];
    const float* Wo = (const float*)d_in[7];
    float* out = (float*)d_out;

    float *proj, *ctx;
    cudaGetSymbolAddress((void**)&proj, g_proj);
    cudaGetSymbolAddress((void**)&ctx,  g_ctx);

    cudaFuncSetAttribute(gemm_tf32, cudaFuncAttributeMaxDynamicSharedMemorySize,
                         GEMM_SMEM);
    cudaFuncSetAttribute(flash_attn_tf32,
                         cudaFuncAttributeMaxDynamicSharedMemorySize, FA_SMEM);

    // Q/K/V projections -> tf32-prerounded fp32
    gemm_tf32<<<dim3(DM / 128, MTOT / 128, 3), 256, GEMM_SMEM>>>(
        q, k, v, Wq, Wk, Wv, proj, 1);

    // full-tf32 attention (64-row CTAs, 3/SM) -> fp32 ctx
    flash_attn_tf32<<<dim3(SEQ / 64, NHEAD, BATCH), 128, FA_SMEM>>>(
        proj, proj + ADM, proj + 2 * ADM, ctx);

    // output projection -> fp32 out
    gemm_tf32<<<dim3(DM / 128, MTOT / 128, 1), 256, GEMM_SMEM>>>(
        ctx, nullptr, nullptr, Wo, nullptr, nullptr, out, 0);
}

// round 9
// speedup vs baseline: 6.2061x; 1.5526x over previous
#include <cuda_runtime.h>
#include <cuda_fp16.h>
#include <cstdint>

#define BATCH 4
#define SEQ   2048
#define DM    1024
#define NHEAD 16
#define DK    64
#define MTOT  (BATCH * SEQ)   // 8192
#define ADM   ((size_t)MTOT * DM)
#define WDM   ((size_t)DM * DM)

// ---------------- scratch (no allocations allowed) ----------------
__device__ __align__(16) __half g_act [3 * ADM];   // fp16 q|k|v inputs
__device__ __align__(16) __half g_w   [4 * WDM];   // fp16 Wq|Wk|Wv|Wo
__device__ __align__(16) __half g_proj[3 * ADM];   // fp16 Q|K|V projections
__device__ __align__(16) __half g_ctx [ADM];       // fp16 attention output

// ---------------- PTX helpers (base sm_103 ISA only) ----------------
__device__ __forceinline__ uint32_t smem_u32(const void* p) {
    uint32_t a;
    asm("{ .reg .u64 t; cvta.to.shared.u64 t, %1; cvt.u32.u64 %0, t; }"
        : "=r"(a) : "l"(p));
    return a;
}

__device__ __forceinline__ void cp16(uint32_t dst, const void* src) {
    asm volatile("cp.async.cg.shared.global [%0], [%1], 16;"
                 :: "r"(dst), "l"(src));
}

__device__ __forceinline__ void ldsm4(uint32_t& r0, uint32_t& r1,
                                      uint32_t& r2, uint32_t& r3, uint32_t addr) {
    asm volatile("ldmatrix.sync.aligned.m8n8.x4.shared.b16 {%0,%1,%2,%3}, [%4];"
                 : "=r"(r0), "=r"(r1), "=r"(r2), "=r"(r3) : "r"(addr));
}

__device__ __forceinline__ void ldsm4t(uint32_t& r0, uint32_t& r1,
                                       uint32_t& r2, uint32_t& r3, uint32_t addr) {
    asm volatile("ldmatrix.sync.aligned.m8n8.x4.trans.shared.b16 {%0,%1,%2,%3}, [%4];"
                 : "=r"(r0), "=r"(r1), "=r"(r2), "=r"(r3) : "r"(addr));
}

__device__ __forceinline__ void mma16816h(float* c, const uint32_t* a,
                                          uint32_t b0, uint32_t b1) {
    asm volatile(
        "mma.sync.aligned.m16n8k16.row.col.f32.f16.f16.f32 "
        "{%0,%1,%2,%3}, {%4,%5,%6,%7}, {%8,%9}, {%0,%1,%2,%3};"
        : "+f"(c[0]), "+f"(c[1]), "+f"(c[2]), "+f"(c[3])
        : "r"(a[0]), "r"(a[1]), "r"(a[2]), "r"(a[3]), "r"(b0), "r"(b1));
}

__device__ __forceinline__ uint32_t pack16(float lo, float hi) {
    uint32_t d;
    asm("cvt.rn.f16x2.f32 %0, %1, %2;" : "=r"(d) : "f"(hi), "f"(lo));
    return d;
}

__device__ __forceinline__ float ex2f(float x) {
    float y;
    asm("ex2.approx.f32 %0, %1;" : "=f"(y) : "f"(x));
    return y;
}

// ---------------- fp32 -> fp16 converters (batched) ----------------
__global__ __launch_bounds__(256) void cvt3(
    const float* __restrict__ x0, const float* __restrict__ x1,
    const float* __restrict__ x2, __half* __restrict__ y, int n4)
{
    int i = blockIdx.x * 256 + threadIdx.x;
    if (i >= n4) return;
    int z = blockIdx.z;
    const float* x = (z == 0) ? x0 : (z == 1) ? x1 : x2;
    float4 v = ((const float4*)x)[i];
    uint2 o = make_uint2(pack16(v.x, v.y), pack16(v.z, v.w));
    ((uint2*)(y + (size_t)z * n4 * 4))[i] = o;
}

__global__ __launch_bounds__(256) void cvt4(
    const float* __restrict__ x0, const float* __restrict__ x1,
    const float* __restrict__ x2, const float* __restrict__ x3,
    __half* __restrict__ y, int n4)
{
    int i = blockIdx.x * 256 + threadIdx.x;
    if (i >= n4) return;
    int z = blockIdx.z;
    const float* x = (z == 0) ? x0 : (z == 1) ? x1 : (z == 2) ? x2 : x3;
    float4 v = ((const float4*)x)[i];
    uint2 o = make_uint2(pack16(v.x, v.y), pack16(v.z, v.w));
    ((uint2*)(y + (size_t)z * n4 * 4))[i] = o;
}

// ---------------- fp16 GEMM: Y[M,N] = A[M,K] @ B[N,K]^T ----------------
// CTA 128x128, BK=32, 256 threads (8 warps 2x4, warp 64x32), 3-stage, occ 2.
#define ROW_B 80                          // 32 fp16 = 64B + 16 pad
#define MAT_B (128 * ROW_B)               // 10240
#define GSTG  (2 * MAT_B)                 // 20480 (A | B)
#define GNST  3
#define GEMM_SMEM (GNST * GSTG)           // 61440

__global__ __launch_bounds__(256, 2)
void gemm_fp16(const __half* __restrict__ Abase, const __half* __restrict__ Bbase,
               float* __restrict__ Y, __half* __restrict__ Yh, int split)
{
    extern __shared__ __align__(128) char smem[];
    const int K = 1024, N = 1024;
    const int tid = threadIdx.x;
    const int w = tid >> 5, lid = tid & 31;
    const int wm = w >> 2, wn = w & 3;
    const int gid = lid >> 2, t4 = lid & 3;
    const int z = blockIdx.z;
    const int brow = blockIdx.y * 128, bcol = blockIdx.x * 128;
    const uint32_t sb = smem_u32(smem);

    const __half* Ap = Abase + (size_t)z * ADM + (size_t)brow * K;
    const __half* Bp = Bbase + (size_t)z * WDM + (size_t)bcol * K;

    const uint32_t lrow = lid & 15;
    const uint32_t lcol = (lid >> 4) * 16;

    auto load_stage = [&](int s) {
        const uint32_t base = sb + (s % GNST) * GSTG;
        const int k0 = s * 32;
#pragma unroll
        for (int t = 0; t < 4; t++) {
            int i = tid + t * 256;
            int m = i >> 9, rem = i & 511;
            int r = rem >> 2, c = rem & 3;
            cp16(base + m * MAT_B + r * ROW_B + c * 16,
                 (m ? Bp : Ap) + (size_t)r * K + k0 + c * 8);
        }
        asm volatile("cp.async.commit_group;" ::: "memory");
    };

    float acc[4][4][4];
#pragma unroll
    for (int mt = 0; mt < 4; mt++)
#pragma unroll
        for (int nt = 0; nt < 4; nt++)
#pragma unroll
            for (int r = 0; r < 4; r++) acc[mt][nt][r] = 0.0f;

    load_stage(0);
    load_stage(1);
    load_stage(2);

#pragma unroll 1
    for (int s = 0; s < 32; s++) {
        asm volatile("cp.async.wait_group 2;" ::: "memory");
        __syncthreads();

        const uint32_t base = sb + (s % GNST) * GSTG;
        const uint32_t a_base = base;
        const uint32_t b_base = base + MAT_B;

#pragma unroll
        for (int ks = 0; ks < 2; ks++) {
            const uint32_t kb = ks * 32 + lcol;
            uint32_t ah[4][4], bh[2][4];
#pragma unroll
            for (int mt = 0; mt < 4; mt++) {
                uint32_t ra = (wm * 64 + mt * 16 + lrow) * ROW_B + kb;
                ldsm4(ah[mt][0], ah[mt][1], ah[mt][2], ah[mt][3], a_base + ra);
            }
#pragma unroll
            for (int g = 0; g < 2; g++) {
                uint32_t rb = (wn * 32 + g * 16 + lrow) * ROW_B + kb;
                ldsm4(bh[g][0], bh[g][1], bh[g][2], bh[g][3], b_base + rb);
            }
#pragma unroll
            for (int mt = 0; mt < 4; mt++)
#pragma unroll
                for (int nt = 0; nt < 4; nt++) {
                    const int g = nt >> 1, o = nt & 1;
                    mma16816h(acc[mt][nt], ah[mt], bh[g][o], bh[g][o + 2]);
                }
        }

        __syncthreads();
        if (s + 3 < 32) load_stage(s + 3);
        else asm volatile("cp.async.commit_group;" ::: "memory");
    }

    const size_t za = (size_t)z * ADM;
#pragma unroll
    for (int mt = 0; mt < 4; mt++) {
        int row0 = brow + wm * 64 + mt * 16 + gid;
#pragma unroll
        for (int nt = 0; nt < 4; nt++) {
            int col = bcol + wn * 32 + nt * 8 + t4 * 2;
            if (split) {
                *(uint32_t*)&Yh[za + (size_t)row0 * N + col] =
                    pack16(acc[mt][nt][0], acc[mt][nt][1]);
                *(uint32_t*)&Yh[za + (size_t)(row0 + 8) * N + col] =
                    pack16(acc[mt][nt][2], acc[mt][nt][3]);
            } else {
                *(float2*)(Y + (size_t)row0 * N + col) =
                    make_float2(acc[mt][nt][0], acc[mt][nt][1]);
                *(float2*)(Y + (size_t)(row0 + 8) * N + col) =
                    make_float2(acc[mt][nt][2], acc[mt][nt][3]);
            }
        }
    }
}

// ---------------- fp16 causal flash attention ----------------
// CTA: 128 q-rows x (b,h); 8 warps x 16 rows; kv tiles of 64, double-buffered.
#define AROWB  144                 // 64 fp16 = 128B + 16 pad
#define AMAT   (64 * AROWB)        // 9216
#define ASTAGE (2 * AMAT)          // K | V = 18432
#define AQ     (128 * AROWB)       // 18432
#define FA_SMEM (AQ + 2 * ASTAGE)  // 55296

__global__ __launch_bounds__(256, 2)
void flash_attn_fp16(const __half* __restrict__ Q, const __half* __restrict__ K,
                     const __half* __restrict__ V, __half* __restrict__ C)
{
    extern __shared__ __align__(128) char smem[];
    const int tid = threadIdx.x, w = tid >> 5, lid = tid & 31;
    const int gid = lid >> 2, t4 = lid & 3;
    const int qi = (SEQ / 128 - 1) - blockIdx.x;   // big tiles first
    const int h = blockIdx.y, b = blockIdx.z;
    const int q0 = qi * 128;
    const int nt = 2 * qi + 2;
    const uint32_t sb = smem_u32(smem);
    const size_t gb = (size_t)b * SEQ * DM + (size_t)h * DK;

    // Q tile -> smem: 128 rows x 64 fp16 (8 x 16B chunks per row)
#pragma unroll
    for (int t = 0; t < 4; t++) {
        int i = tid + t * 256;
        int r = i >> 3, c = i & 7;
        cp16(sb + r * AROWB + c * 16, Q + gb + (size_t)(q0 + r) * DM + c * 8);
    }
    asm volatile("cp.async.commit_group;" ::: "memory");

    auto load_kv = [&](int jt, int buf) {
        const uint32_t st = sb + AQ + buf * ASTAGE;
        const int k0 = jt * 64;
#pragma unroll
        for (int t = 0; t < 4; t++) {
            int i = tid + t * 256;
            int m = i >> 9, rem = i & 511, r = rem >> 3, c = rem & 7;
            cp16(st + m * AMAT + r * AROWB + c * 16,
                 (m ? V : K) + gb + (size_t)(k0 + r) * DM + c * 8);
        }
        asm volatile("cp.async.commit_group;" ::: "memory");
    };

    load_kv(0, 0);

    uint32_t qa[4][4];
    float Oa[8][4];
    float m0 = -1e30f, m1 = -1e30f, l0 = 0.f, l1 = 0.f;
#pragma unroll
    for (int nf = 0; nf < 8; nf++)
#pragma unroll
        for (int c = 0; c < 4; c++) Oa[nf][c] = 0.f;

    const float SC = 0.18033688011112042f;   // 0.125 * log2(e)
    const uint32_t qaddr = sb + (w * 16 + (lid & 15)) * AROWB + ((lid >> 4) << 4);
    const uint32_t lrowoff = (((lid >> 3) & 1) * 8 + (lid & 7)) * AROWB + ((lid >> 4) << 4);

    for (int jt = 0; jt < nt; jt++) {
        if (jt + 1 < nt) {
            load_kv(jt + 1, (jt + 1) & 1);
            asm volatile("cp.async.wait_group 1;" ::: "memory");
        } else {
            asm volatile("cp.async.wait_group 0;" ::: "memory");
        }
        __syncthreads();

        const uint32_t st = sb + AQ + (jt & 1) * ASTAGE;
        const int k0 = jt * 64;
        const bool diag = (jt >= nt - 2);
        const int lim = 16 * w + 15 - (k0 - q0);      // valid on diag tiles
        const int nfm = diag ? min(8, max(0, (lim >> 3) + 1)) : 8;
        const int ksm = diag ? min(4, max(0, (lim >> 4) + 1)) : 4;

        if (jt == 0) {
#pragma unroll
            for (int ks = 0; ks < 4; ks++)
                ldsm4(qa[ks][0], qa[ks][1], qa[ks][2], qa[ks][3], qaddr + ks * 32);
        }

        // ---- S = Q K^T (fp16 single)
        float S[8][4];
#pragma unroll
        for (int nf = 0; nf < 8; nf++)
#pragma unroll
            for (int c = 0; c < 4; c++) S[nf][c] = 0.f;

#pragma unroll
        for (int g = 0; g < 4; g++) {
            if (2 * g >= nfm) break;
            uint32_t kh[4][4];
#pragma unroll
            for (int ks = 0; ks < 4; ks++) {
                uint32_t ka = st + g * (16 * AROWB) + lrowoff + ks * 32;
                ldsm4(kh[ks][0], kh[ks][1], kh[ks][2], kh[ks][3], ka);
            }
#pragma unroll
            for (int ks = 0; ks < 4; ks++)
#pragma unroll
                for (int o = 0; o < 2; o++) {
                    if (2 * g + o >= nfm) break;
                    mma16816h(S[2 * g + o], qa[ks], kh[ks][o], kh[ks][o + 2]);
                }
        }

        // ---- softmax (base-2 domain)
        const int row0 = q0 + w * 16 + gid;
#pragma unroll
        for (int nf = 0; nf < 8; nf++) {
            int coln = k0 + nf * 8 + 2 * t4;
            S[nf][0] *= SC; S[nf][1] *= SC; S[nf][2] *= SC; S[nf][3] *= SC;
            if (diag) {
                if (coln     > row0)     S[nf][0] = -1e30f;
                if (coln + 1 > row0)     S[nf][1] = -1e30f;
                if (coln     > row0 + 8) S[nf][2] = -1e30f;
                if (coln + 1 > row0 + 8) S[nf][3] = -1e30f;
            }
        }
        float mx0 = -1e30f, mx1 = -1e30f;
#pragma unroll
        for (int nf = 0; nf < 8; nf++) {
            mx0 = fmaxf(mx0, fmaxf(S[nf][0], S[nf][1]));
            mx1 = fmaxf(mx1, fmaxf(S[nf][2], S[nf][3]));
        }
        mx0 = fmaxf(mx0, __shfl_xor_sync(0xffffffffu, mx0, 1));
        mx0 = fmaxf(mx0, __shfl_xor_sync(0xffffffffu, mx0, 2));
        mx1 = fmaxf(mx1, __shfl_xor_sync(0xffffffffu, mx1, 1));
        mx1 = fmaxf(mx1, __shfl_xor_sync(0xffffffffu, mx1, 2));

        float m0n = fmaxf(m0, mx0), m1n = fmaxf(m1, mx1);
        float a0 = ex2f(m0 - m0n), a1 = ex2f(m1 - m1n);
        m0 = m0n; m1 = m1n;

        float rs0 = 0.f, rs1 = 0.f;
        uint32_t ph[4][4];
#pragma unroll
        for (int ks = 0; ks < 4; ks++)
#pragma unroll
            for (int half = 0; half < 2; half++) {
                int nf = 2 * ks + half;
                float p0 = ex2f(S[nf][0] - m0n);
                float p1 = ex2f(S[nf][1] - m0n);
                float p2 = ex2f(S[nf][2] - m1n);
                float p3 = ex2f(S[nf][3] - m1n);
                rs0 += p0 + p1; rs1 += p2 + p3;
                ph[ks][2 * half]     = pack16(p0, p1);
                ph[ks][2 * half + 1] = pack16(p2, p3);
            }
        rs0 += __shfl_xor_sync(0xffffffffu, rs0, 1);
        rs0 += __shfl_xor_sync(0xffffffffu, rs0, 2);
        rs1 += __shfl_xor_sync(0xffffffffu, rs1, 1);
        rs1 += __shfl_xor_sync(0xffffffffu, rs1, 2);
        l0 = l0 * a0 + rs0;
        l1 = l1 * a1 + rs1;
#pragma unroll
        for (int nf = 0; nf < 8; nf++) {
            Oa[nf][0] *= a0; Oa[nf][1] *= a0;
            Oa[nf][2] *= a1; Oa[nf][3] *= a1;
        }

        // ---- O += P V (fp16 single); skip all-zero k-groups on diag tiles
#pragma unroll
        for (int g = 0; g < 4; g++) {
            uint32_t vh[4][4];
#pragma unroll
            for (int ks = 0; ks < 4; ks++) {
                if (ks >= ksm) break;
                uint32_t va = st + AMAT + ks * (16 * AROWB) + lrowoff + g * 32;
                ldsm4t(vh[ks][0], vh[ks][1], vh[ks][2], vh[ks][3], va);
            }
#pragma unroll
            for (int ks = 0; ks < 4; ks++) {
                if (ks >= ksm) break;
#pragma unroll
                for (int o = 0; o < 2; o++)
                    mma16816h(Oa[2 * g + o], ph[ks], vh[ks][2 * o], vh[ks][2 * o + 1]);
            }
        }
        __syncthreads();
    }

    // ---- epilogue: ctx = O / l -> fp16
    float il0 = 1.f / l0, il1 = 1.f / l1;
    const int row0 = q0 + w * 16 + gid;
#pragma unroll
    for (int nf = 0; nf < 8; nf++) {
        int col = nf * 8 + 2 * t4;
        size_t ad0 = gb + (size_t)row0 * DM + col;
        size_t ad1 = gb + (size_t)(row0 + 8) * DM + col;
        *(uint32_t*)&C[ad0] = pack16(Oa[nf][0] * il0, Oa[nf][1] * il0);
        *(uint32_t*)&C[ad1] = pack16(Oa[nf][2] * il1, Oa[nf][3] * il1);
    }
}

// ---------------- launch ----------------
extern "C" void kernel_launch(void* const* d_in, const int* in_sizes, int n_in,
                              void* d_out, int out_size)
{
    const float* q  = (const float*)d_in[0];
    const float* k  = (const float*)d_in[1];
    const float* v  = (const float*)d_in[2];
    const float* Wq = (const float*)d_in[4];
    const float* Wk = (const float*)d_in[5];
    const float* Wv = (const float*)d_in[6];
    const float* Wo = (const float*)d_in[7];
    float* out = (float*)d_out;

    __half *act, *wgt, *proj, *ctx;
    cudaGetSymbolAddress((void**)&act,  g_act);
    cudaGetSymbolAddress((void**)&wgt,  g_w);
    cudaGetSymbolAddress((void**)&proj, g_proj);
    cudaGetSymbolAddress((void**)&ctx,  g_ctx);

    cudaFuncSetAttribute(gemm_fp16, cudaFuncAttributeMaxDynamicSharedMemorySize,
                         GEMM_SMEM);
    cudaFuncSetAttribute(flash_attn_fp16,
                         cudaFuncAttributeMaxDynamicSharedMemorySize, FA_SMEM);

    const int NA4 = (int)(ADM / 4);
    const int NW4 = (int)(WDM / 4);

    cvt3<<<dim3(NA4 / 256, 1, 3), 256>>>(q, k, v, act, NA4);
    cvt4<<<dim3(NW4 / 256, 1, 4), 256>>>(Wq, Wk, Wv, Wo, wgt, NW4);

    // Q/K/V projections (fp16) -> fp16
    gemm_fp16<<<dim3(DM / 128, MTOT / 128, 3), 256, GEMM_SMEM>>>(
        act, wgt, nullptr, proj, 1);

    // fp16 attention -> fp16 ctx
    flash_attn_fp16<<<dim3(SEQ / 128, NHEAD, BATCH), 256, FA_SMEM>>>(
        proj, proj + ADM, proj + 2 * ADM, ctx);

    // output projection -> fp32 out (ctx at z=0, Wo passed directly)
    gemm_fp16<<<dim3(DM / 128, MTOT / 128, 1), 256, GEMM_SMEM>>>(
        ctx, wgt + 3 * WDM, out, nullptr, 0);
}

// round 10
// speedup vs baseline: 7.0489x; 1.1358x over previous
#include <cuda_runtime.h>
#include <cuda_fp16.h>
#include <cstdint>

#define BATCH 4
#define SEQ   2048
#define DM    1024
#define NHEAD 16
#define DK    64
#define MTOT  (BATCH * SEQ)   // 8192
#define ADM   ((size_t)MTOT * DM)
#define WDM   ((size_t)DM * DM)

// ---------------- scratch (no allocations allowed) ----------------
__device__ __align__(16) __half g_act [3 * ADM];   // fp16 q|k|v inputs
__device__ __align__(16) __half g_w   [4 * WDM];   // fp16 Wq|Wk|Wv|Wo
__device__ __align__(16) __half g_proj[3 * ADM];   // fp16 Q|K|V projections
__device__ __align__(16) __half g_ctx [ADM];       // fp16 attention output

// ---------------- PTX helpers (base sm_103 ISA only) ----------------
__device__ __forceinline__ uint32_t smem_u32(const void* p) {
    uint32_t a;
    asm("{ .reg .u64 t; cvta.to.shared.u64 t, %1; cvt.u32.u64 %0, t; }"
        : "=r"(a) : "l"(p));
    return a;
}

__device__ __forceinline__ void cp16(uint32_t dst, const void* src) {
    asm volatile("cp.async.cg.shared.global [%0], [%1], 16;"
                 :: "r"(dst), "l"(src));
}

__device__ __forceinline__ void ldsm4(uint32_t& r0, uint32_t& r1,
                                      uint32_t& r2, uint32_t& r3, uint32_t addr) {
    asm volatile("ldmatrix.sync.aligned.m8n8.x4.shared.b16 {%0,%1,%2,%3}, [%4];"
                 : "=r"(r0), "=r"(r1), "=r"(r2), "=r"(r3) : "r"(addr));
}

__device__ __forceinline__ void ldsm4t(uint32_t& r0, uint32_t& r1,
                                       uint32_t& r2, uint32_t& r3, uint32_t addr) {
    asm volatile("ldmatrix.sync.aligned.m8n8.x4.trans.shared.b16 {%0,%1,%2,%3}, [%4];"
                 : "=r"(r0), "=r"(r1), "=r"(r2), "=r"(r3) : "r"(addr));
}

__device__ __forceinline__ void mma16816h(float* c, const uint32_t* a,
                                          uint32_t b0, uint32_t b1) {
    asm volatile(
        "mma.sync.aligned.m16n8k16.row.col.f32.f16.f16.f32 "
        "{%0,%1,%2,%3}, {%4,%5,%6,%7}, {%8,%9}, {%0,%1,%2,%3};"
        : "+f"(c[0]), "+f"(c[1]), "+f"(c[2]), "+f"(c[3])
        : "r"(a[0]), "r"(a[1]), "r"(a[2]), "r"(a[3]), "r"(b0), "r"(b1));
}

__device__ __forceinline__ uint32_t pack16(float lo, float hi) {
    uint32_t d;
    asm("cvt.rn.f16x2.f32 %0, %1, %2;" : "=r"(d) : "f"(hi), "f"(lo));
    return d;
}

__device__ __forceinline__ uint32_t ex2h2(uint32_t x) {
    uint32_t y;
    asm("ex2.approx.f16x2 %0, %1;" : "=r"(y) : "r"(x));
    return y;
}

__device__ __forceinline__ uint32_t hadd2(uint32_t a, uint32_t b) {
    uint32_t d;
    asm("add.rn.f16x2 %0, %1, %2;" : "=r"(d) : "r"(a), "r"(b));
    return d;
}

__device__ __forceinline__ float ex2f(float x) {
    float y;
    asm("ex2.approx.f32 %0, %1;" : "=f"(y) : "f"(x));
    return y;
}

// ---------------- fp32 -> fp16 converters (batched) ----------------
__global__ __launch_bounds__(256) void cvt3(
    const float* __restrict__ x0, const float* __restrict__ x1,
    const float* __restrict__ x2, __half* __restrict__ y, int n4)
{
    int i = blockIdx.x * 256 + threadIdx.x;
    if (i >= n4) return;
    int z = blockIdx.z;
    const float* x = (z == 0) ? x0 : (z == 1) ? x1 : x2;
    float4 v = ((const float4*)x)[i];
    uint2 o = make_uint2(pack16(v.x, v.y), pack16(v.z, v.w));
    ((uint2*)(y + (size_t)z * n4 * 4))[i] = o;
}

__global__ __launch_bounds__(256) void cvt4(
    const float* __restrict__ x0, const float* __restrict__ x1,
    const float* __restrict__ x2, const float* __restrict__ x3,
    __half* __restrict__ y, int n4)
{
    int i = blockIdx.x * 256 + threadIdx.x;
    if (i >= n4) return;
    int z = blockIdx.z;
    const float* x = (z == 0) ? x0 : (z == 1) ? x1 : (z == 2) ? x2 : x3;
    float4 v = ((const float4*)x)[i];
    uint2 o = make_uint2(pack16(v.x, v.y), pack16(v.z, v.w));
    ((uint2*)(y + (size_t)z * n4 * 4))[i] = o;
}

// ---------------- fp16 GEMM: Y[M,N] = A[M,K] @ B[N,K]^T ----------------
// CTA 128x128, BK=64, 256 threads (8 warps 2x4, warp 64x32), 2-stage, occ 2.
#define ROW_B 144                         // 64 fp16 = 128B + 16 pad
#define MAT_B (128 * ROW_B)               // 18432
#define GSTG  (2 * MAT_B)                 // 36864 (A | B)
#define GNST  2
#define GEMM_SMEM (GNST * GSTG)           // 73728
#define QSCALE 0.18033688011112042f       // 0.125 * log2(e)

__global__ __launch_bounds__(256, 2)
void gemm_fp16(const __half* __restrict__ Abase, const __half* __restrict__ Bbase,
               float* __restrict__ Y, __half* __restrict__ Yh, int split)
{
    extern __shared__ __align__(128) char smem[];
    const int K = 1024, N = 1024;
    const int tid = threadIdx.x;
    const int w = tid >> 5, lid = tid & 31;
    const int wm = w >> 2, wn = w & 3;
    const int gid = lid >> 2, t4 = lid & 3;
    const int z = blockIdx.z;
    const int brow = blockIdx.y * 128, bcol = blockIdx.x * 128;
    const uint32_t sb = smem_u32(smem);

    const __half* Ap = Abase + (size_t)z * ADM + (size_t)brow * K;
    const __half* Bp = Bbase + (size_t)z * WDM + (size_t)bcol * K;

    const uint32_t lrow = lid & 15;
    const uint32_t lcol = (lid >> 4) * 16;

    auto load_stage = [&](int s) {
        const uint32_t base = sb + (s & 1) * GSTG;
        const int k0 = s * 64;
#pragma unroll
        for (int t = 0; t < 8; t++) {
            int i = tid + t * 256;
            int m = i >> 10, rem = i & 1023;
            int r = rem >> 3, c = rem & 7;
            cp16(base + m * MAT_B + r * ROW_B + c * 16,
                 (m ? Bp : Ap) + (size_t)r * K + k0 + c * 8);
        }
        asm volatile("cp.async.commit_group;" ::: "memory");
    };

    float acc[4][4][4];
#pragma unroll
    for (int mt = 0; mt < 4; mt++)
#pragma unroll
        for (int nt = 0; nt < 4; nt++)
#pragma unroll
            for (int r = 0; r < 4; r++) acc[mt][nt][r] = 0.0f;

    load_stage(0);
    load_stage(1);

#pragma unroll 1
    for (int s = 0; s < 16; s++) {
        asm volatile("cp.async.wait_group 1;" ::: "memory");
        __syncthreads();

        const uint32_t base = sb + (s & 1) * GSTG;
        const uint32_t a_base = base;
        const uint32_t b_base = base + MAT_B;

#pragma unroll
        for (int ks = 0; ks < 4; ks++) {
            const uint32_t kb = ks * 32 + lcol;
            uint32_t ah[4][4], bh[2][4];
#pragma unroll
            for (int mt = 0; mt < 4; mt++) {
                uint32_t ra = (wm * 64 + mt * 16 + lrow) * ROW_B + kb;
                ldsm4(ah[mt][0], ah[mt][1], ah[mt][2], ah[mt][3], a_base + ra);
            }
#pragma unroll
            for (int g = 0; g < 2; g++) {
                uint32_t rb = (wn * 32 + g * 16 + lrow) * ROW_B + kb;
                ldsm4(bh[g][0], bh[g][1], bh[g][2], bh[g][3], b_base + rb);
            }
#pragma unroll
            for (int mt = 0; mt < 4; mt++)
#pragma unroll
                for (int nt = 0; nt < 4; nt++) {
                    const int g = nt >> 1, o = nt & 1;
                    mma16816h(acc[mt][nt], ah[mt], bh[g][o], bh[g][o + 2]);
                }
        }

        __syncthreads();
        if (s + 2 < 16) load_stage(s + 2);
        else asm volatile("cp.async.commit_group;" ::: "memory");
    }

    const size_t za = (size_t)z * ADM;
    // Pre-scale Q (z==0 of the split launch) by 0.125*log2(e) for the
    // base-2-domain softmax; K/V unscaled.
    const float osc = (split && z == 0) ? QSCALE : 1.0f;
#pragma unroll
    for (int mt = 0; mt < 4; mt++) {
        int row0 = brow + wm * 64 + mt * 16 + gid;
#pragma unroll
        for (int nt = 0; nt < 4; nt++) {
            int col = bcol + wn * 32 + nt * 8 + t4 * 2;
            if (split) {
                *(uint32_t*)&Yh[za + (size_t)row0 * N + col] =
                    pack16(acc[mt][nt][0] * osc, acc[mt][nt][1] * osc);
                *(uint32_t*)&Yh[za + (size_t)(row0 + 8) * N + col] =
                    pack16(acc[mt][nt][2] * osc, acc[mt][nt][3] * osc);
            } else {
                *(float2*)(Y + (size_t)row0 * N + col) =
                    make_float2(acc[mt][nt][0], acc[mt][nt][1]);
                *(float2*)(Y + (size_t)(row0 + 8) * N + col) =
                    make_float2(acc[mt][nt][2], acc[mt][nt][3]);
            }
        }
    }
}

// ---------------- fp16 causal flash attention ----------------
// CTA: 128 q-rows x (b,h); 8 warps x 16 rows; kv tiles of 64, double-buffered.
// Q pre-scaled by 0.125*log2(e): S is already in base-2 softmax domain.
#define AROWB  144                 // 64 fp16 = 128B + 16 pad
#define AMAT   (64 * AROWB)        // 9216
#define ASTAGE (2 * AMAT)          // K | V = 18432
#define AQ     (128 * AROWB)       // 18432
#define FA_SMEM (AQ + 2 * ASTAGE)  // 55296

__global__ __launch_bounds__(256, 2)
void flash_attn_fp16(const __half* __restrict__ Q, const __half* __restrict__ K,
                     const __half* __restrict__ V, __half* __restrict__ C)
{
    extern __shared__ __align__(128) char smem[];
    const int tid = threadIdx.x, w = tid >> 5, lid = tid & 31;
    const int gid = lid >> 2, t4 = lid & 3;
    const int qi = (SEQ / 128 - 1) - blockIdx.x;   // big tiles first
    const int h = blockIdx.y, b = blockIdx.z;
    const int q0 = qi * 128;
    const int nt = 2 * qi + 2;
    const uint32_t sb = smem_u32(smem);
    const size_t gb = (size_t)b * SEQ * DM + (size_t)h * DK;

    // Q tile -> smem: 128 rows x 64 fp16
#pragma unroll
    for (int t = 0; t < 4; t++) {
        int i = tid + t * 256;
        int r = i >> 3, c = i & 7;
        cp16(sb + r * AROWB + c * 16, Q + gb + (size_t)(q0 + r) * DM + c * 8);
    }
    asm volatile("cp.async.commit_group;" ::: "memory");

    auto load_kv = [&](int jt, int buf) {
        const uint32_t st = sb + AQ + buf * ASTAGE;
        const int k0 = jt * 64;
#pragma unroll
        for (int t = 0; t < 4; t++) {
            int i = tid + t * 256;
            int m = i >> 9, rem = i & 511, r = rem >> 3, c = rem & 7;
            cp16(st + m * AMAT + r * AROWB + c * 16,
                 (m ? V : K) + gb + (size_t)(k0 + r) * DM + c * 8);
        }
        asm volatile("cp.async.commit_group;" ::: "memory");
    };

    load_kv(0, 0);

    uint32_t qa[4][4];
    float Oa[8][4];
    float m0 = -1e30f, m1 = -1e30f, l0 = 0.f, l1 = 0.f;
#pragma unroll
    for (int nf = 0; nf < 8; nf++)
#pragma unroll
        for (int c = 0; c < 4; c++) Oa[nf][c] = 0.f;

    const uint32_t qaddr = sb + (w * 16 + (lid & 15)) * AROWB + ((lid >> 4) << 4);
    const uint32_t lrowoff = (((lid >> 3) & 1) * 8 + (lid & 7)) * AROWB + ((lid >> 4) << 4);

    for (int jt = 0; jt < nt; jt++) {
        if (jt + 1 < nt) {
            load_kv(jt + 1, (jt + 1) & 1);
            asm volatile("cp.async.wait_group 1;" ::: "memory");
        } else {
            asm volatile("cp.async.wait_group 0;" ::: "memory");
        }
        __syncthreads();

        const uint32_t st = sb + AQ + (jt & 1) * ASTAGE;
        const int k0 = jt * 64;
        const bool diag = (jt >= nt - 2);
        const int lim = 16 * w + 15 - (k0 - q0);      // valid on diag tiles
        const int nfm = diag ? min(8, max(0, (lim >> 3) + 1)) : 8;
        const int ksm = diag ? min(4, max(0, (lim >> 4) + 1)) : 4;

        if (jt == 0) {
#pragma unroll
            for (int ks = 0; ks < 4; ks++)
                ldsm4(qa[ks][0], qa[ks][1], qa[ks][2], qa[ks][3], qaddr + ks * 32);
        }

        // ---- S = Q K^T (Q pre-scaled; S in base-2 domain)
        float S[8][4];
#pragma unroll
        for (int nf = 0; nf < 8; nf++)
#pragma unroll
            for (int c = 0; c < 4; c++) S[nf][c] = 0.f;

#pragma unroll
        for (int g = 0; g < 4; g++) {
            if (2 * g >= nfm) break;
            uint32_t kh[4][4];
#pragma unroll
            for (int ks = 0; ks < 4; ks++) {
                uint32_t ka = st + g * (16 * AROWB) + lrowoff + ks * 32;
                ldsm4(kh[ks][0], kh[ks][1], kh[ks][2], kh[ks][3], ka);
            }
#pragma unroll
            for (int ks = 0; ks < 4; ks++)
#pragma unroll
                for (int o = 0; o < 2; o++) {
                    if (2 * g + o >= nfm) break;
                    mma16816h(S[2 * g + o], qa[ks], kh[ks][o], kh[ks][o + 2]);
                }
        }

        // ---- masking + row max
        const int row0 = q0 + w * 16 + gid;
        if (diag) {
#pragma unroll
            for (int nf = 0; nf < 8; nf++) {
                int coln = k0 + nf * 8 + 2 * t4;
                if (coln     > row0)     S[nf][0] = -1e30f;
                if (coln + 1 > row0)     S[nf][1] = -1e30f;
                if (coln     > row0 + 8) S[nf][2] = -1e30f;
                if (coln + 1 > row0 + 8) S[nf][3] = -1e30f;
            }
        }
        float mx0 = -1e30f, mx1 = -1e30f;
#pragma unroll
        for (int nf = 0; nf < 8; nf++) {
            mx0 = fmaxf(mx0, fmaxf(S[nf][0], S[nf][1]));
            mx1 = fmaxf(mx1, fmaxf(S[nf][2], S[nf][3]));
        }
        mx0 = fmaxf(mx0, __shfl_xor_sync(0xffffffffu, mx0, 1));
        mx0 = fmaxf(mx0, __shfl_xor_sync(0xffffffffu, mx0, 2));
        mx1 = fmaxf(mx1, __shfl_xor_sync(0xffffffffu, mx1, 1));
        mx1 = fmaxf(mx1, __shfl_xor_sync(0xffffffffu, mx1, 2));

        float m0n = fmaxf(m0, mx0), m1n = fmaxf(m1, mx1);
        float a0 = ex2f(m0 - m0n), a1 = ex2f(m1 - m1n);
        m0 = m0n; m1 = m1n;

        // ---- P = 2^(S - m) via packed f16x2 ex2; rowsums in f16x2
        uint32_t rsa0 = 0, rsa1 = 0;
        uint32_t ph[4][4];
#pragma unroll
        for (int ks = 0; ks < 4; ks++)
#pragma unroll
            for (int half = 0; half < 2; half++) {
                int nf = 2 * ks + half;
                uint32_t p01 = ex2h2(pack16(S[nf][0] - m0n, S[nf][1] - m0n));
                uint32_t p23 = ex2h2(pack16(S[nf][2] - m1n, S[nf][3] - m1n));
                ph[ks][2 * half]     = p01;
                ph[ks][2 * half + 1] = p23;
                rsa0 = hadd2(rsa0, p01);
                rsa1 = hadd2(rsa1, p23);
            }
        __half2 h0 = *(__half2*)&rsa0;
        __half2 h1 = *(__half2*)&rsa1;
        float rs0 = __low2float(h0) + __high2float(h0);
        float rs1 = __low2float(h1) + __high2float(h1);
        rs0 += __shfl_xor_sync(0xffffffffu, rs0, 1);
        rs0 += __shfl_xor_sync(0xffffffffu, rs0, 2);
        rs1 += __shfl_xor_sync(0xffffffffu, rs1, 1);
        rs1 += __shfl_xor_sync(0xffffffffu, rs1, 2);
        l0 = l0 * a0 + rs0;
        l1 = l1 * a1 + rs1;
#pragma unroll
        for (int nf = 0; nf < 8; nf++) {
            Oa[nf][0] *= a0; Oa[nf][1] *= a0;
            Oa[nf][2] *= a1; Oa[nf][3] *= a1;
        }

        // ---- O += P V; skip all-zero k-groups on diag tiles
#pragma unroll
        for (int g = 0; g < 4; g++) {
            uint32_t vh[4][4];
#pragma unroll
            for (int ks = 0; ks < 4; ks++) {
                if (ks >= ksm) break;
                uint32_t va = st + AMAT + ks * (16 * AROWB) + lrowoff + g * 32;
                ldsm4t(vh[ks][0], vh[ks][1], vh[ks][2], vh[ks][3], va);
            }
#pragma unroll
            for (int ks = 0; ks < 4; ks++) {
                if (ks >= ksm) break;
#pragma unroll
                for (int o = 0; o < 2; o++)
                    mma16816h(Oa[2 * g + o], ph[ks], vh[ks][2 * o], vh[ks][2 * o + 1]);
            }
        }
        __syncthreads();
    }

    // ---- epilogue: ctx = O / l -> fp16
    float il0 = 1.f / l0, il1 = 1.f / l1;
    const int row0 = q0 + w * 16 + gid;
#pragma unroll
    for (int nf = 0; nf < 8; nf++) {
        int col = nf * 8 + 2 * t4;
        size_t ad0 = gb + (size_t)row0 * DM + col;
        size_t ad1 = gb + (size_t)(row0 + 8) * DM + col;
        *(uint32_t*)&C[ad0] = pack16(Oa[nf][0] * il0, Oa[nf][1] * il0);
        *(uint32_t*)&C[ad1] = pack16(Oa[nf][2] * il1, Oa[nf][3] * il1);
    }
}

// ---------------- launch ----------------
extern "C" void kernel_launch(void* const* d_in, const int* in_sizes, int n_in,
                              void* d_out, int out_size)
{
    const float* q  = (const float*)d_in[0];
    const float* k  = (const float*)d_in[1];
    const float* v  = (const float*)d_in[2];
    const float* Wq = (const float*)d_in[4];
    const float* Wk = (const float*)d_in[5];
    const float* Wv = (const float*)d_in[6];
    const float* Wo = (const float*)d_in[7];
    float* out = (float*)d_out;

    __half *act, *wgt, *proj, *ctx;
    cudaGetSymbolAddress((void**)&act,  g_act);
    cudaGetSymbolAddress((void**)&wgt,  g_w);
    cudaGetSymbolAddress((void**)&proj, g_proj);
    cudaGetSymbolAddress((void**)&ctx,  g_ctx);

    cudaFuncSetAttribute(gemm_fp16, cudaFuncAttributeMaxDynamicSharedMemorySize,
                         GEMM_SMEM);
    cudaFuncSetAttribute(flash_attn_fp16,
                         cudaFuncAttributeMaxDynamicSharedMemorySize, FA_SMEM);

    const int NA4 = (int)(ADM / 4);
    const int NW4 = (int)(WDM / 4);

    cvt3<<<dim3(NA4 / 256, 1, 3), 256>>>(q, k, v, act, NA4);
    cvt4<<<dim3(NW4 / 256, 1, 4), 256>>>(Wq, Wk, Wv, Wo, wgt, NW4);

    // Q/K/V projections (fp16) -> fp16 (Q pre-scaled for base-2 softmax)
    gemm_fp16<<<dim3(DM / 128, MTOT / 128, 3), 256, GEMM_SMEM>>>(
        act, wgt, nullptr, proj, 1);

    // fp16 attention -> fp16 ctx
    flash_attn_fp16<<<dim3(SEQ / 128, NHEAD, BATCH), 256, FA_SMEM>>>(
        proj, proj + ADM, proj + 2 * ADM, ctx);

    // output projection -> fp32 out
    gemm_fp16<<<dim3(DM / 128, MTOT / 128, 1), 256, GEMM_SMEM>>>(
        ctx, wgt + 3 * WDM, out, nullptr, 0);
}